// round 9
// baseline (speedup 1.0000x reference)
#include <cuda_runtime.h>
#include <cuda_bf16.h>
#include <cstdint>
#include <math.h>

// Problem dims (fixed)
#define BB   64
#define SS   4096
#define DECD 512
#define ENCD 1024
#define AD   256
#define NEG_INF_F (-1e10f)

#define CTX_CHUNKS 16
#define CTX_SROWS  (SS / CTX_CHUNKS)   // 256

// ---------------- scratch ----------------
__device__ float g_dec_proj[BB * AD];
__device__ float g_scores[BB * SS];
__device__ __align__(16) float g_ctx_part[CTX_CHUNKS * BB * ENCD];
__device__ int   g_mask_is_u8;
// W_enc split to bf16 hi/lo, [k][n] row-major (k=0..1023, n=0..255)
__device__ __align__(16) __nv_bfloat16 g_w_hi[ENCD * AD];
__device__ __align__(16) __nv_bfloat16 g_w_lo[ENCD * AD];

// ---------------- helpers ----------------
__device__ __forceinline__ uint32_t smem_u32(const void* p) {
    uint32_t a;
    asm("{ .reg .u64 t; cvta.to.shared.u64 t, %1; cvt.u32.u64 %0, t; }" : "=r"(a) : "l"(p));
    return a;
}
__device__ __forceinline__ void ldsm_x4(uint32_t* r, uint32_t addr) {
    asm volatile("ldmatrix.sync.aligned.m8n8.x4.shared.b16 {%0,%1,%2,%3}, [%4];"
        : "=r"(r[0]), "=r"(r[1]), "=r"(r[2]), "=r"(r[3]) : "r"(addr));
}
__device__ __forceinline__ void ldsm_x4t(uint32_t* r, uint32_t addr) {
    asm volatile("ldmatrix.sync.aligned.m8n8.x4.trans.shared.b16 {%0,%1,%2,%3}, [%4];"
        : "=r"(r[0]), "=r"(r[1]), "=r"(r[2]), "=r"(r[3]) : "r"(addr));
}
__device__ __forceinline__ void mma16816(float* d, const uint32_t* a, const uint32_t* b) {
    asm volatile("mma.sync.aligned.m16n8k16.row.col.f32.bf16.bf16.f32 "
        "{%0,%1,%2,%3}, {%4,%5,%6,%7}, {%8,%9}, {%0,%1,%2,%3};"
        : "+f"(d[0]), "+f"(d[1]), "+f"(d[2]), "+f"(d[3])
        : "r"(a[0]), "r"(a[1]), "r"(a[2]), "r"(a[3]), "r"(b[0]), "r"(b[1]));
}
__device__ __forceinline__ void cp16(uint32_t sdst, const void* gsrc) {
    asm volatile("cp.async.cg.shared.global [%0], [%1], 16;" :: "r"(sdst), "l"(gsrc));
}
#define CP_COMMIT() asm volatile("cp.async.commit_group;" ::: "memory")
#define CP_WAIT0()  asm volatile("cp.async.wait_group 0;" ::: "memory")

__device__ __forceinline__ uint32_t pkbf(__nv_bfloat16 a, __nv_bfloat16 b) {
    uint16_t ua = *(uint16_t*)&a, ub = *(uint16_t*)&b;
    return (uint32_t)ua | ((uint32_t)ub << 16);
}
// accurate fast tanh via MUFU ex2 (rel err ~1e-6)
__device__ __forceinline__ float tanh_f(float x) {
    float e = __expf(2.0f * x);
    return 1.0f - __fdividef(2.0f, e + 1.0f);
}

// ---------------- kernel 0: detect mask dtype ----------------
__global__ void k_detect_mask(const unsigned int* __restrict__ m) {
    unsigned int v = m[threadIdx.x];
    int any = __syncthreads_or(v > 1u);
    if (threadIdx.x == 0) g_mask_is_u8 = any;
}

// ---------------- kernel 0b: split W_enc into bf16 hi/lo ----------------
__global__ void k_prep_w(const float* __restrict__ We) {
    int k = blockIdx.x;             // 0..1023
    int n = threadIdx.x;            // 0..255
    float x = We[(size_t)k * AD + n];
    __nv_bfloat16 h = __float2bfloat16_rn(x);
    __nv_bfloat16 l = __float2bfloat16_rn(x - __bfloat162float(h));
    g_w_hi[(size_t)k * AD + n] = h;
    g_w_lo[(size_t)k * AD + n] = l;
}

// ---------------- kernel 1: dec_proj ----------------
__global__ void k_dec_proj(const float* __restrict__ dh, const float* __restrict__ Wd) {
    int b = blockIdx.x;
    int a = threadIdx.x;
    const float* dhb = dh + b * DECD;
    float acc = 0.f;
#pragma unroll 8
    for (int d = 0; d < DECD; d++)
        acc = fmaf(dhb[d], Wd[d * AD + a], acc);
    g_dec_proj[b * AD + a] = acc;
}

// ---------------- kernel 2: mma.sync split-bf16 scores GEMM, double-buffered ----------------
// CTA: 256 thr / 8 warps, tile M=128 x N=256. Warp tile 64x64 (2M x 4N warps).
// K chunks of 32. W via cp.async ping-pong; E via register prefetch + in-kernel split.
#define SE_STRIDE 80     // bytes per E row (64 data + 16 pad)
#define SW_STRIDE 528    // bytes per W row (512 data + 16 pad)
#define EBUF   (128 * SE_STRIDE)   // 10240
#define WBUF   (32 * SW_STRIDE)    // 16896
// dynamic smem layout (byte offsets)
#define O_EH   0
#define O_EL   (O_EH + 2 * EBUF)          // 20480
#define O_WH   (O_EL + 2 * EBUF)          // 40960
#define O_WL   (O_WH + 2 * WBUF)          // 74752
#define O_SV   (O_WL + 2 * WBUF)          // 108544
#define O_SDP  (O_SV + AD * 4)            // 109568
#define O_SP   (O_SDP + AD * 4)           // 110592
#define SMEM_SC (O_SP + 4 * 128 * 4)      // 112640

__global__ __launch_bounds__(256, 1)
void k_scores_mma(const float* __restrict__ enc, const float* __restrict__ v) {
    extern __shared__ __align__(16) uint8_t smem[];
    const uint32_t sb = smem_u32(smem);

    const int tid  = threadIdx.x;
    const int w    = tid >> 5;
    const int lane = tid & 31;
    const int b    = blockIdx.y;
    const int s0   = blockIdx.x * 128;

    const int wm = (w & 1) * 64;     // warp M offset
    const int wn = (w >> 1);         // warp N quarter (64 cols at wn*64)

    float* sv  = (float*)(smem + O_SV);
    float* sdp = (float*)(smem + O_SDP);
    float* sp  = (float*)(smem + O_SP);       // [4][128]
    sv[tid]  = v[tid];
    sdp[tid] = g_dec_proj[b * AD + tid];

    const float* Eb = enc + ((size_t)b * SS + s0) * ENCD;

    // ldmatrix per-lane offsets
    const int li = lane >> 3, l7 = lane & 7;
    uint32_t aOff[4];
#pragma unroll
    for (int mt = 0; mt < 4; mt++) {
        int m = wm + mt * 16 + (li & 1) * 8 + l7;
        int k = (li >> 1) * 8;
        aOff[mt] = m * SE_STRIDE + k * 2;
    }
    uint32_t bOff[4];
#pragma unroll
    for (int p = 0; p < 4; p++) {
        int k = (li & 1) * 8 + l7;
        int n = wn * 64 + p * 16 + (li >> 1) * 8;
        bOff[p] = k * SW_STRIDE + n * 2;
    }

    float acc[4][8][4];
#pragma unroll
    for (int mt = 0; mt < 4; mt++)
#pragma unroll
        for (int j = 0; j < 8; j++)
#pragma unroll
            for (int r = 0; r < 4; r++) acc[mt][j][r] = 0.f;

    // load-index mapping
    const int er = tid >> 3, ecg = (tid & 7) * 4;     // E: 32 row-groups x 8 col-groups

    // ---- prologue: E0 -> regs, W0 -> smem buf0 via cp.async ----
    float4 ev[4];
#pragma unroll
    for (int j = 0; j < 4; j++)
        ev[j] = *(const float4*)(Eb + (size_t)(er + j * 32) * ENCD + ecg);
#pragma unroll
    for (int i = 0; i < 4; i++) {
        int idx = tid + i * 256;
        int row = idx >> 5, seg = idx & 31;
        cp16(sb + O_WH + row * SW_STRIDE + seg * 16, g_w_hi + (size_t)row * AD + seg * 8);
        cp16(sb + O_WL + row * SW_STRIDE + seg * 16, g_w_lo + (size_t)row * AD + seg * 8);
    }
    CP_COMMIT();

#pragma unroll 1
    for (int c = 0; c < 32; c++) {
        const int buf = c & 1;
        uint8_t* eh = smem + O_EH + buf * EBUF;
        uint8_t* el = smem + O_EL + buf * EBUF;
        const uint32_t uEh = sb + O_EH + buf * EBUF;
        const uint32_t uEl = sb + O_EL + buf * EBUF;
        const uint32_t uWh = sb + O_WH + buf * WBUF;
        const uint32_t uWl = sb + O_WL + buf * WBUF;

        CP_WAIT0();                 // W(c) resident
        // store E(c) from regs, split hi/lo
#pragma unroll
        for (int j = 0; j < 4; j++) {
            float4 x = ev[j];
            __nv_bfloat16 h0 = __float2bfloat16_rn(x.x), h1 = __float2bfloat16_rn(x.y);
            __nv_bfloat16 h2 = __float2bfloat16_rn(x.z), h3 = __float2bfloat16_rn(x.w);
            __nv_bfloat16 l0 = __float2bfloat16_rn(x.x - __bfloat162float(h0));
            __nv_bfloat16 l1 = __float2bfloat16_rn(x.y - __bfloat162float(h1));
            __nv_bfloat16 l2 = __float2bfloat16_rn(x.z - __bfloat162float(h2));
            __nv_bfloat16 l3 = __float2bfloat16_rn(x.w - __bfloat162float(h3));
            uint32_t off = (er + j * 32) * SE_STRIDE + ecg * 2;
            *(uint2*)(eh + off) = make_uint2(pkbf(h0, h1), pkbf(h2, h3));
            *(uint2*)(el + off) = make_uint2(pkbf(l0, l1), pkbf(l2, l3));
        }
        __syncthreads();

        // prefetch chunk c+1 (E regs + W cp.async into other buffer)
        if (c < 31) {
            const int k1 = (c + 1) * 32;
#pragma unroll
            for (int j = 0; j < 4; j++)
                ev[j] = *(const float4*)(Eb + (size_t)(er + j * 32) * ENCD + k1 + ecg);
            const uint32_t wb = sb + ((c + 1) & 1) * WBUF;
#pragma unroll
            for (int i = 0; i < 4; i++) {
                int idx = tid + i * 256;
                int row = idx >> 5, seg = idx & 31;
                cp16(wb + O_WH + row * SW_STRIDE + seg * 16,
                     g_w_hi + (size_t)(k1 + row) * AD + seg * 8);
                cp16(wb + O_WL + row * SW_STRIDE + seg * 16,
                     g_w_lo + (size_t)(k1 + row) * AD + seg * 8);
            }
            CP_COMMIT();
        }

        // ---- compute: 2 x k16 ----
#pragma unroll
        for (int ks = 0; ks < 2; ks++) {
            const uint32_t dA = ks * 32;
            const uint32_t dB = ks * 16 * SW_STRIDE;
            uint32_t AH[4][4], AL[4][4];
#pragma unroll
            for (int mt = 0; mt < 4; mt++) {
                ldsm_x4(AH[mt], uEh + aOff[mt] + dA);
                ldsm_x4(AL[mt], uEl + aOff[mt] + dA);
            }
#pragma unroll
            for (int p = 0; p < 4; p++) {
                uint32_t BH[4], BL[4];
                ldsm_x4t(BH, uWh + bOff[p] + dB);
                ldsm_x4t(BL, uWl + bOff[p] + dB);
#pragma unroll
                for (int mt = 0; mt < 4; mt++) {
#pragma unroll
                    for (int nt = 0; nt < 2; nt++) {
                        float* d = acc[mt][p * 2 + nt];
                        mma16816(d, AH[mt], BH + nt * 2);
                        mma16816(d, AH[mt], BL + nt * 2);
                        mma16816(d, AL[mt], BH + nt * 2);
                    }
                }
            }
        }
        __syncthreads();
    }

    // ---- epilogue: score_m = sum_n v[n] * tanh(dp[n] + D[m][n]) ----
    const int g = lane >> 2, tig = lane & 3;
#pragma unroll
    for (int mt = 0; mt < 4; mt++) {
        float pA = 0.f, pB = 0.f;
#pragma unroll
        for (int j = 0; j < 8; j++) {
            int c0 = wn * 64 + j * 8 + tig * 2;
            float v0 = sv[c0], v1 = sv[c0 + 1];
            float d0 = sdp[c0], d1 = sdp[c0 + 1];
            pA += v0 * tanh_f(d0 + acc[mt][j][0]);
            pA += v1 * tanh_f(d1 + acc[mt][j][1]);
            pB += v0 * tanh_f(d0 + acc[mt][j][2]);
            pB += v1 * tanh_f(d1 + acc[mt][j][3]);
        }
        pA += __shfl_xor_sync(0xffffffffu, pA, 1);
        pA += __shfl_xor_sync(0xffffffffu, pA, 2);
        pB += __shfl_xor_sync(0xffffffffu, pB, 1);
        pB += __shfl_xor_sync(0xffffffffu, pB, 2);
        if (tig == 0) {
            int rA = wm + mt * 16 + g;
            sp[wn * 128 + rA]     = pA;
            sp[wn * 128 + rA + 8] = pB;
        }
    }
    __syncthreads();
    if (tid < 128) {
        float s = sp[tid] + sp[128 + tid] + sp[256 + tid] + sp[384 + tid];
        g_scores[(size_t)b * SS + s0 + tid] = s;
    }
}

// ---------------- kernel 3: mask + softmax ----------------
__global__ __launch_bounds__(256) void k_softmax(const void* __restrict__ mask,
                                                 float* __restrict__ out_w) {
    const int b = blockIdx.x;
    const int tid = threadIdx.x;
    const float* row = g_scores + (size_t)b * SS;
    const int u8 = g_mask_is_u8;
    const uint8_t* m8 = (const uint8_t*)mask;
    const int*     m32 = (const int*)mask;

    float vals[16];
    float mx = -INFINITY;
#pragma unroll
    for (int i = 0; i < 16; i++) {
        size_t idx = (size_t)b * SS + tid + i * 256;
        int msk = u8 ? (int)m8[idx] : m32[idx];
        vals[i] = msk ? NEG_INF_F : row[tid + i * 256];
        mx = fmaxf(mx, vals[i]);
    }
#pragma unroll
    for (int m = 16; m; m >>= 1)
        mx = fmaxf(mx, __shfl_xor_sync(0xffffffffu, mx, m));
    __shared__ float redm[8];
    if ((tid & 31) == 0) redm[tid >> 5] = mx;
    __syncthreads();
    mx = redm[0];
#pragma unroll
    for (int i = 1; i < 8; i++) mx = fmaxf(mx, redm[i]);

    float sum = 0.f;
#pragma unroll
    for (int i = 0; i < 16; i++) {
        vals[i] = expf(vals[i] - mx);
        sum += vals[i];
    }
#pragma unroll
    for (int m = 16; m; m >>= 1)
        sum += __shfl_xor_sync(0xffffffffu, sum, m);
    __shared__ float reds[8];
    if ((tid & 31) == 0) reds[tid >> 5] = sum;
    __syncthreads();
    sum = 0.f;
#pragma unroll
    for (int i = 0; i < 8; i++) sum += reds[i];

    float inv = 1.f / sum;
#pragma unroll
    for (int i = 0; i < 16; i++)
        out_w[(size_t)b * SS + tid + i * 256] = vals[i] * inv;
}

// ---------------- kernel 4: context partials ----------------
__global__ __launch_bounds__(256) void k_context_part(const float* __restrict__ enc,
                                                      const float* __restrict__ w) {
    const int chunk = blockIdx.x;
    const int b = blockIdx.y;
    const int tid = threadIdx.x;
    const int s0 = chunk * CTX_SROWS;

    __shared__ float ws[CTX_SROWS];
    ws[tid] = w[(size_t)b * SS + s0 + tid];
    __syncthreads();

    const float* Eb = enc + ((size_t)b * SS + s0) * ENCD;
    const int e0 = tid * 4;

    float4 acc = make_float4(0.f, 0.f, 0.f, 0.f);
#pragma unroll 4
    for (int s = 0; s < CTX_SROWS; s++) {
        float wv = ws[s];
        float4 x = *(const float4*)(Eb + (size_t)s * ENCD + e0);
        acc.x = fmaf(wv, x.x, acc.x);
        acc.y = fmaf(wv, x.y, acc.y);
        acc.z = fmaf(wv, x.z, acc.z);
        acc.w = fmaf(wv, x.w, acc.w);
    }
    *(float4*)(g_ctx_part + ((size_t)chunk * BB + b) * ENCD + e0) = acc;
}

// ---------------- kernel 5: reduce partials ----------------
__global__ void k_context_reduce(float* __restrict__ out_ctx) {
    int i = blockIdx.x * 256 + threadIdx.x;
    float acc = 0.f;
#pragma unroll
    for (int c = 0; c < CTX_CHUNKS; c++)
        acc += g_ctx_part[(size_t)c * BB * ENCD + i];
    out_ctx[i] = acc;
}

// ---------------- launch ----------------
extern "C" void kernel_launch(void* const* d_in, const int* in_sizes, int n_in,
                              void* d_out, int out_size) {
    const float* dh   = (const float*)d_in[0];
    const float* enc  = (const float*)d_in[1];
    const void*  mask = d_in[2];
    const float* Wd   = (const float*)d_in[3];
    const float* We   = (const float*)d_in[4];
    const float* v    = (const float*)d_in[5];

    float* out     = (float*)d_out;
    float* out_ctx = out;
    float* out_w   = out + BB * ENCD;

    cudaFuncSetAttribute(k_scores_mma, cudaFuncAttributeMaxDynamicSharedMemorySize, SMEM_SC);

    k_detect_mask<<<1, 1024>>>((const unsigned int*)mask);
    k_prep_w<<<ENCD, 256>>>(We);
    k_dec_proj<<<BB, 256>>>(dh, Wd);

    dim3 g2(SS / 128, BB);
    k_scores_mma<<<g2, 256, SMEM_SC>>>(enc, v);

    k_softmax<<<BB, 256>>>(mask, out_w);

    dim3 g4(CTX_CHUNKS, BB);
    k_context_part<<<g4, 256>>>(enc, out_w);
    k_context_reduce<<<(BB * ENCD) / 256, 256>>>(out_ctx);
}

// round 10
// speedup vs baseline: 1.0957x; 1.0957x over previous
#include <cuda_runtime.h>
#include <cuda_bf16.h>
#include <cstdint>
#include <math.h>

// Problem dims (fixed)
#define BB   64
#define SS   4096
#define DECD 512
#define ENCD 1024
#define AD   256
#define NEG_INF_F (-1e10f)

#define CTX_CHUNKS 16
#define CTX_SROWS  (SS / CTX_CHUNKS)   // 256

// ---------------- scratch ----------------
__device__ float g_dec_proj[BB * AD];
__device__ float g_scores[BB * SS];
__device__ __align__(16) float g_ctx_part[CTX_CHUNKS * BB * ENCD];
__device__ int   g_mask_is_u8;
// W_enc split to bf16 hi/lo, [k][n] row-major
__device__ __align__(16) __nv_bfloat16 g_w_hi[ENCD * AD];
__device__ __align__(16) __nv_bfloat16 g_w_lo[ENCD * AD];

// ---------------- helpers ----------------
__device__ __forceinline__ uint32_t smem_u32(const void* p) {
    uint32_t a;
    asm("{ .reg .u64 t; cvta.to.shared.u64 t, %1; cvt.u32.u64 %0, t; }" : "=r"(a) : "l"(p));
    return a;
}
__device__ __forceinline__ void ldsm_x4(uint32_t* r, uint32_t addr) {
    asm volatile("ldmatrix.sync.aligned.m8n8.x4.shared.b16 {%0,%1,%2,%3}, [%4];"
        : "=r"(r[0]), "=r"(r[1]), "=r"(r[2]), "=r"(r[3]) : "r"(addr));
}
__device__ __forceinline__ void ldsm_x4t(uint32_t* r, uint32_t addr) {
    asm volatile("ldmatrix.sync.aligned.m8n8.x4.trans.shared.b16 {%0,%1,%2,%3}, [%4];"
        : "=r"(r[0]), "=r"(r[1]), "=r"(r[2]), "=r"(r[3]) : "r"(addr));
}
__device__ __forceinline__ void mma16816(float* d, const uint32_t* a, const uint32_t* b) {
    asm volatile("mma.sync.aligned.m16n8k16.row.col.f32.bf16.bf16.f32 "
        "{%0,%1,%2,%3}, {%4,%5,%6,%7}, {%8,%9}, {%0,%1,%2,%3};"
        : "+f"(d[0]), "+f"(d[1]), "+f"(d[2]), "+f"(d[3])
        : "r"(a[0]), "r"(a[1]), "r"(a[2]), "r"(a[3]), "r"(b[0]), "r"(b[1]));
}
__device__ __forceinline__ void cp16(uint32_t sdst, const void* gsrc) {
    asm volatile("cp.async.cg.shared.global [%0], [%1], 16;" :: "r"(sdst), "l"(gsrc));
}
#define CP_COMMIT() asm volatile("cp.async.commit_group;" ::: "memory")
#define CP_WAIT0()  asm volatile("cp.async.wait_group 0;" ::: "memory")

__device__ __forceinline__ uint32_t pkbf(__nv_bfloat16 a, __nv_bfloat16 b) {
    uint16_t ua = *(uint16_t*)&a, ub = *(uint16_t*)&b;
    return (uint32_t)ua | ((uint32_t)ub << 16);
}
__device__ __forceinline__ float tanh_f(float x) {
    float e = __expf(2.0f * x);
    return 1.0f - __fdividef(2.0f, e + 1.0f);
}

// ---------------- kernel 0: detect mask dtype ----------------
__global__ void k_detect_mask(const unsigned int* __restrict__ m) {
    unsigned int v = m[threadIdx.x];
    int any = __syncthreads_or(v > 1u);
    if (threadIdx.x == 0) g_mask_is_u8 = any;
}

// ---------------- kernel 0b: split W_enc into bf16 hi/lo ----------------
__global__ void k_prep_w(const float* __restrict__ We) {
    int k = blockIdx.x;
    int n = threadIdx.x;
    float x = We[(size_t)k * AD + n];
    __nv_bfloat16 h = __float2bfloat16_rn(x);
    __nv_bfloat16 l = __float2bfloat16_rn(x - __bfloat162float(h));
    g_w_hi[(size_t)k * AD + n] = h;
    g_w_lo[(size_t)k * AD + n] = l;
}

// ---------------- kernel 1: dec_proj ----------------
__global__ void k_dec_proj(const float* __restrict__ dh, const float* __restrict__ Wd) {
    int b = blockIdx.x;
    int a = threadIdx.x;
    const float* dhb = dh + b * DECD;
    float acc = 0.f;
#pragma unroll 8
    for (int d = 0; d < DECD; d++)
        acc = fmaf(dhb[d], Wd[d * AD + a], acc);
    g_dec_proj[b * AD + a] = acc;
}

// ---------------- kernel 2: mma.sync split-bf16 scores GEMM, cp.async pipelined ----------------
// CTA: 256 thr / 8 warps, tile M=64 x N=256. Warp tile 32x64 (round-7 occupancy config).
// K chunks of 32. W hi/lo + raw E double-buffered via cp.async; E split reads smem.
#define SE_STRIDE 80     // bytes per split-E row (64 data + 16 pad)
#define SW_STRIDE 528    // bytes per W row (512 data + 16 pad)
#define WBUF   (32 * SW_STRIDE)    // 16896
#define ERBUF  (64 * 128)          // raw E: 64 rows x 32 f32 = 8192
#define ESBUF  (64 * SE_STRIDE)    // split E: 5120
// dynamic smem layout
#define O_WH   0
#define O_WL   (O_WH + 2 * WBUF)          // 33792
#define O_ER   (O_WL + 2 * WBUF)          // 67584
#define O_EH   (O_ER + 2 * ERBUF)         // 83968
#define O_EL   (O_EH + ESBUF)             // 89088
#define O_SV   (O_EL + ESBUF)             // 94208
#define O_SDP  (O_SV + AD * 4)            // 95232
#define O_SP   (O_SDP + AD * 4)           // 96256
#define SMEM_SC (O_SP + 4 * 64 * 4)       // 97280

__global__ __launch_bounds__(256, 2)
void k_scores_mma(const float* __restrict__ enc, const float* __restrict__ v) {
    extern __shared__ __align__(16) uint8_t smem[];
    const uint32_t sb = smem_u32(smem);

    const int tid  = threadIdx.x;
    const int w    = tid >> 5;
    const int lane = tid & 31;
    const int b    = blockIdx.y;
    const int s0   = blockIdx.x * 64;

    const int wm = (w & 1) * 32;     // warp M offset
    const int wn = (w >> 1);         // warp N quarter (64 cols at wn*64)

    float* sv  = (float*)(smem + O_SV);
    float* sdp = (float*)(smem + O_SDP);
    float* sp  = (float*)(smem + O_SP);       // [4][64]
    sv[tid]  = v[tid];
    sdp[tid] = g_dec_proj[b * AD + tid];

    const float* Eb = enc + ((size_t)b * SS + s0) * ENCD;

    // ldmatrix per-lane offsets
    const int li = lane >> 3, l7 = lane & 7;
    uint32_t aOff[2];
#pragma unroll
    for (int mt = 0; mt < 2; mt++) {
        int m = wm + mt * 16 + (li & 1) * 8 + l7;
        int k = (li >> 1) * 8;
        aOff[mt] = m * SE_STRIDE + k * 2;
    }
    uint32_t bOff[4];
#pragma unroll
    for (int p = 0; p < 4; p++) {
        int k = (li & 1) * 8 + l7;
        int n = wn * 64 + p * 16 + (li >> 1) * 8;
        bOff[p] = k * SW_STRIDE + n * 2;
    }

    float acc[2][8][4];
#pragma unroll
    for (int mt = 0; mt < 2; mt++)
#pragma unroll
        for (int j = 0; j < 8; j++)
#pragma unroll
            for (int r = 0; r < 4; r++) acc[mt][j][r] = 0.f;

    // cp.async mappings
    const int wrow = tid >> 5, wc16 = tid & 31;       // W: row-part, 16B segment
    const int e_row = tid >> 2, e_seg = tid & 3;      // raw E: 64 rows x 8 segs, 2 iters
    const int er = tid >> 3, ecg = (tid & 7) * 4;     // convert: row group, f32 col group

    // ---- prologue: chunk 0 ----
#pragma unroll
    for (int i = 0; i < 4; i++) {
        int idx = tid + i * 256;
        int row = idx >> 5, seg = idx & 31;
        cp16(sb + O_WH + row * SW_STRIDE + seg * 16, g_w_hi + (size_t)row * AD + seg * 8);
        cp16(sb + O_WL + row * SW_STRIDE + seg * 16, g_w_lo + (size_t)row * AD + seg * 8);
    }
#pragma unroll
    for (int i = 0; i < 2; i++) {
        int idx = tid + i * 256;
        int row = idx >> 3, seg = idx & 7;
        cp16(sb + O_ER + row * 128 + seg * 16, Eb + (size_t)row * ENCD + seg * 4);
    }
    CP_COMMIT();

#pragma unroll 1
    for (int c = 0; c < 32; c++) {
        const int buf = c & 1;
        const uint32_t uEh = sb + O_EH;
        const uint32_t uEl = sb + O_EL;
        const uint32_t uWh = sb + O_WH + buf * WBUF;
        const uint32_t uWl = sb + O_WL + buf * WBUF;

        CP_WAIT0();
        __syncthreads();          // chunk-c data visible to all; compute(c-1) fully done

        // convert raw E(c) -> split hi/lo (reads smem, transient regs only)
        {
            const uint8_t* erb = smem + O_ER + buf * ERBUF;
#pragma unroll
            for (int j = 0; j < 2; j++) {
                int r = er + j * 32;
                float4 x = *(const float4*)(erb + r * 128 + ecg * 4);
                __nv_bfloat16 h0 = __float2bfloat16_rn(x.x), h1 = __float2bfloat16_rn(x.y);
                __nv_bfloat16 h2 = __float2bfloat16_rn(x.z), h3 = __float2bfloat16_rn(x.w);
                __nv_bfloat16 l0 = __float2bfloat16_rn(x.x - __bfloat162float(h0));
                __nv_bfloat16 l1 = __float2bfloat16_rn(x.y - __bfloat162float(h1));
                __nv_bfloat16 l2 = __float2bfloat16_rn(x.z - __bfloat162float(h2));
                __nv_bfloat16 l3 = __float2bfloat16_rn(x.w - __bfloat162float(h3));
                uint32_t off = r * SE_STRIDE + ecg * 2;
                *(uint2*)(smem + O_EH + off) = make_uint2(pkbf(h0, h1), pkbf(h2, h3));
                *(uint2*)(smem + O_EL + off) = make_uint2(pkbf(l0, l1), pkbf(l2, l3));
            }
        }

        // prefetch chunk c+1 into other buffers
        if (c < 31) {
            const int k1 = (c + 1) * 32;
            const uint32_t ob = (c + 1) & 1;
#pragma unroll
            for (int i = 0; i < 4; i++) {
                int idx = tid + i * 256;
                int row = idx >> 5, seg = idx & 31;
                cp16(sb + O_WH + ob * WBUF + row * SW_STRIDE + seg * 16,
                     g_w_hi + (size_t)(k1 + row) * AD + seg * 8);
                cp16(sb + O_WL + ob * WBUF + row * SW_STRIDE + seg * 16,
                     g_w_lo + (size_t)(k1 + row) * AD + seg * 8);
            }
#pragma unroll
            for (int i = 0; i < 2; i++) {
                int idx = tid + i * 256;
                int row = idx >> 3, seg = idx & 7;
                cp16(sb + O_ER + ob * ERBUF + row * 128 + seg * 16,
                     Eb + (size_t)row * ENCD + k1 + seg * 4);
            }
            CP_COMMIT();
        }
        __syncthreads();          // split E ready

        // ---- compute: 2 x k16 ----
#pragma unroll
        for (int ks = 0; ks < 2; ks++) {
            const uint32_t dA = ks * 32;
            const uint32_t dB = ks * 16 * SW_STRIDE;
            uint32_t AH[2][4], AL[2][4];
#pragma unroll
            for (int mt = 0; mt < 2; mt++) {
                ldsm_x4(AH[mt], uEh + aOff[mt] + dA);
                ldsm_x4(AL[mt], uEl + aOff[mt] + dA);
            }
#pragma unroll
            for (int p = 0; p < 4; p++) {
                uint32_t BH[4], BL[4];
                ldsm_x4t(BH, uWh + bOff[p] + dB);
                ldsm_x4t(BL, uWl + bOff[p] + dB);
#pragma unroll
                for (int mt = 0; mt < 2; mt++) {
#pragma unroll
                    for (int nt = 0; nt < 2; nt++) {
                        float* d = acc[mt][p * 2 + nt];
                        mma16816(d, AH[mt], BH + nt * 2);
                        mma16816(d, AH[mt], BL + nt * 2);
                        mma16816(d, AL[mt], BH + nt * 2);
                    }
                }
            }
        }
        // no trailing sync: next iteration's post-wait sync covers WAR on split E / W buffers
    }

    __syncthreads();

    // ---- epilogue ----
    const int g = lane >> 2, tig = lane & 3;
#pragma unroll
    for (int mt = 0; mt < 2; mt++) {
        float pA = 0.f, pB = 0.f;
#pragma unroll
        for (int j = 0; j < 8; j++) {
            int c0 = wn * 64 + j * 8 + tig * 2;
            float v0 = sv[c0], v1 = sv[c0 + 1];
            float d0 = sdp[c0], d1 = sdp[c0 + 1];
            pA += v0 * tanh_f(d0 + acc[mt][j][0]);
            pA += v1 * tanh_f(d1 + acc[mt][j][1]);
            pB += v0 * tanh_f(d0 + acc[mt][j][2]);
            pB += v1 * tanh_f(d1 + acc[mt][j][3]);
        }
        pA += __shfl_xor_sync(0xffffffffu, pA, 1);
        pA += __shfl_xor_sync(0xffffffffu, pA, 2);
        pB += __shfl_xor_sync(0xffffffffu, pB, 1);
        pB += __shfl_xor_sync(0xffffffffu, pB, 2);
        if (tig == 0) {
            int rA = wm + mt * 16 + g;
            sp[wn * 64 + rA]     = pA;
            sp[wn * 64 + rA + 8] = pB;
        }
    }
    __syncthreads();
    if (tid < 64) {
        float s = sp[tid] + sp[64 + tid] + sp[128 + tid] + sp[192 + tid];
        g_scores[(size_t)b * SS + s0 + tid] = s;
    }
}

// ---------------- kernel 3: mask + softmax ----------------
__global__ __launch_bounds__(256) void k_softmax(const void* __restrict__ mask,
                                                 float* __restrict__ out_w) {
    const int b = blockIdx.x;
    const int tid = threadIdx.x;
    const float* row = g_scores + (size_t)b * SS;
    const int u8 = g_mask_is_u8;
    const uint8_t* m8 = (const uint8_t*)mask;
    const int*     m32 = (const int*)mask;

    float vals[16];
    float mx = -INFINITY;
#pragma unroll
    for (int i = 0; i < 16; i++) {
        size_t idx = (size_t)b * SS + tid + i * 256;
        int msk = u8 ? (int)m8[idx] : m32[idx];
        vals[i] = msk ? NEG_INF_F : row[tid + i * 256];
        mx = fmaxf(mx, vals[i]);
    }
#pragma unroll
    for (int m = 16; m; m >>= 1)
        mx = fmaxf(mx, __shfl_xor_sync(0xffffffffu, mx, m));
    __shared__ float redm[8];
    if ((tid & 31) == 0) redm[tid >> 5] = mx;
    __syncthreads();
    mx = redm[0];
#pragma unroll
    for (int i = 1; i < 8; i++) mx = fmaxf(mx, redm[i]);

    float sum = 0.f;
#pragma unroll
    for (int i = 0; i < 16; i++) {
        vals[i] = expf(vals[i] - mx);
        sum += vals[i];
    }
#pragma unroll
    for (int m = 16; m; m >>= 1)
        sum += __shfl_xor_sync(0xffffffffu, sum, m);
    __shared__ float reds[8];
    if ((tid & 31) == 0) reds[tid >> 5] = sum;
    __syncthreads();
    sum = 0.f;
#pragma unroll
    for (int i = 0; i < 8; i++) sum += reds[i];

    float inv = 1.f / sum;
#pragma unroll
    for (int i = 0; i < 16; i++)
        out_w[(size_t)b * SS + tid + i * 256] = vals[i] * inv;
}

// ---------------- kernel 4: context partials ----------------
__global__ __launch_bounds__(256) void k_context_part(const float* __restrict__ enc,
                                                      const float* __restrict__ w) {
    const int chunk = blockIdx.x;
    const int b = blockIdx.y;
    const int tid = threadIdx.x;
    const int s0 = chunk * CTX_SROWS;

    __shared__ float ws[CTX_SROWS];
    ws[tid] = w[(size_t)b * SS + s0 + tid];
    __syncthreads();

    const float* Eb = enc + ((size_t)b * SS + s0) * ENCD;
    const int e0 = tid * 4;

    float4 acc = make_float4(0.f, 0.f, 0.f, 0.f);
#pragma unroll 4
    for (int s = 0; s < CTX_SROWS; s++) {
        float wv = ws[s];
        float4 x = *(const float4*)(Eb + (size_t)s * ENCD + e0);
        acc.x = fmaf(wv, x.x, acc.x);
        acc.y = fmaf(wv, x.y, acc.y);
        acc.z = fmaf(wv, x.z, acc.z);
        acc.w = fmaf(wv, x.w, acc.w);
    }
    *(float4*)(g_ctx_part + ((size_t)chunk * BB + b) * ENCD + e0) = acc;
}

// ---------------- kernel 5: reduce partials ----------------
__global__ void k_context_reduce(float* __restrict__ out_ctx) {
    int i = blockIdx.x * 256 + threadIdx.x;
    float acc = 0.f;
#pragma unroll
    for (int c = 0; c < CTX_CHUNKS; c++)
        acc += g_ctx_part[(size_t)c * BB * ENCD + i];
    out_ctx[i] = acc;
}

// ---------------- launch ----------------
extern "C" void kernel_launch(void* const* d_in, const int* in_sizes, int n_in,
                              void* d_out, int out_size) {
    const float* dh   = (const float*)d_in[0];
    const float* enc  = (const float*)d_in[1];
    const void*  mask = d_in[2];
    const float* Wd   = (const float*)d_in[3];
    const float* We   = (const float*)d_in[4];
    const float* v    = (const float*)d_in[5];

    float* out     = (float*)d_out;
    float* out_ctx = out;
    float* out_w   = out + BB * ENCD;

    cudaFuncSetAttribute(k_scores_mma, cudaFuncAttributeMaxDynamicSharedMemorySize, SMEM_SC);

    k_detect_mask<<<1, 1024>>>((const unsigned int*)mask);
    k_prep_w<<<ENCD, 256>>>(We);
    k_dec_proj<<<BB, 256>>>(dh, Wd);

    dim3 g2(SS / 64, BB);
    k_scores_mma<<<g2, 256, SMEM_SC>>>(enc, v);

    k_softmax<<<BB, 256>>>(mask, out_w);

    dim3 g4(CTX_CHUNKS, BB);
    k_context_part<<<g4, 256>>>(enc, out_w);
    k_context_reduce<<<(BB * ENCD) / 256, 256>>>(out_ctx);
}

// round 13
// speedup vs baseline: 1.1000x; 1.0039x over previous
#include <cuda_runtime.h>
#include <cuda_bf16.h>
#include <cstdint>
#include <math.h>

// Problem dims (fixed)
#define BB   64
#define SS   4096
#define DECD 512
#define ENCD 1024
#define AD   256
#define NEG_INF_F (-1e10f)

#define CTX_CHUNKS 16
#define CTX_SROWS  (SS / CTX_CHUNKS)   // 256

// ---------------- scratch ----------------
__device__ float g_dec_proj[BB * AD];
__device__ float g_scores[BB * SS];
__device__ __align__(16) float g_ctx_part[CTX_CHUNKS * BB * ENCD];
__device__ int   g_mask_is_u8;
// W_enc split to bf16 hi/lo, [k][n] row-major
__device__ __align__(16) __nv_bfloat16 g_w_hi[ENCD * AD];
__device__ __align__(16) __nv_bfloat16 g_w_lo[ENCD * AD];

// ---------------- helpers ----------------
__device__ __forceinline__ uint32_t smem_u32(const void* p) {
    uint32_t a;
    asm("{ .reg .u64 t; cvta.to.shared.u64 t, %1; cvt.u32.u64 %0, t; }" : "=r"(a) : "l"(p));
    return a;
}
__device__ __forceinline__ void ldsm_x4(uint32_t* r, uint32_t addr) {
    asm volatile("ldmatrix.sync.aligned.m8n8.x4.shared.b16 {%0,%1,%2,%3}, [%4];"
        : "=r"(r[0]), "=r"(r[1]), "=r"(r[2]), "=r"(r[3]) : "r"(addr));
}
__device__ __forceinline__ void ldsm_x4t(uint32_t* r, uint32_t addr) {
    asm volatile("ldmatrix.sync.aligned.m8n8.x4.trans.shared.b16 {%0,%1,%2,%3}, [%4];"
        : "=r"(r[0]), "=r"(r[1]), "=r"(r[2]), "=r"(r[3]) : "r"(addr));
}
__device__ __forceinline__ void mma16816(float* d, const uint32_t* a, const uint32_t* b) {
    asm volatile("mma.sync.aligned.m16n8k16.row.col.f32.bf16.bf16.f32 "
        "{%0,%1,%2,%3}, {%4,%5,%6,%7}, {%8,%9}, {%0,%1,%2,%3};"
        : "+f"(d[0]), "+f"(d[1]), "+f"(d[2]), "+f"(d[3])
        : "r"(a[0]), "r"(a[1]), "r"(a[2]), "r"(a[3]), "r"(b[0]), "r"(b[1]));
}
__device__ __forceinline__ void cp16(uint32_t sdst, const void* gsrc) {
    asm volatile("cp.async.cg.shared.global [%0], [%1], 16;" :: "r"(sdst), "l"(gsrc));
}
#define CP_COMMIT() asm volatile("cp.async.commit_group;" ::: "memory")
#define CP_WAIT0()  asm volatile("cp.async.wait_group 0;" ::: "memory")

__device__ __forceinline__ uint32_t pkbf(__nv_bfloat16 a, __nv_bfloat16 b) {
    uint16_t ua = *(uint16_t*)&a, ub = *(uint16_t*)&b;
    return (uint32_t)ua | ((uint32_t)ub << 16);
}
__device__ __forceinline__ float tanh_f(float x) {
    float e = __expf(2.0f * x);
    return 1.0f - __fdividef(2.0f, e + 1.0f);
}

// ---------------- kernel 0: detect mask dtype ----------------
__global__ void k_detect_mask(const unsigned int* __restrict__ m) {
    unsigned int v = m[threadIdx.x];
    int any = __syncthreads_or(v > 1u);
    if (threadIdx.x == 0) g_mask_is_u8 = any;
}

// ---------------- kernel 0b: split W_enc into bf16 hi/lo ----------------
__global__ void k_prep_w(const float* __restrict__ We) {
    int k = blockIdx.x;
    int n = threadIdx.x;
    float x = We[(size_t)k * AD + n];
    __nv_bfloat16 h = __float2bfloat16_rn(x);
    __nv_bfloat16 l = __float2bfloat16_rn(x - __bfloat162float(h));
    g_w_hi[(size_t)k * AD + n] = h;
    g_w_lo[(size_t)k * AD + n] = l;
}

// ---------------- kernel 1: dec_proj ----------------
__global__ void k_dec_proj(const float* __restrict__ dh, const float* __restrict__ Wd) {
    int b = blockIdx.x;
    int a = threadIdx.x;
    const float* dhb = dh + b * DECD;
    float acc = 0.f;
#pragma unroll 8
    for (int d = 0; d < DECD; d++)
        acc = fmaf(dhb[d], Wd[d * AD + a], acc);
    g_dec_proj[b * AD + a] = acc;
}

// ---------------- kernel 2: mma.sync split-bf16 scores GEMM (proven r9 schedule,
//                  term-major MMA ordering) ----------------
// CTA: 256 thr / 8 warps, tile M=64 x N=256. Warp tile 32x64, 2 CTAs/SM.
#define SE_STRIDE 80     // bytes per split-E row (64 data + 16 pad)
#define SW_STRIDE 528    // bytes per W row (512 data + 16 pad)
#define WBUF   (32 * SW_STRIDE)    // 16896
#define ERBUF  (64 * 128)          // raw E: 64 rows x 32 f32 = 8192
#define ESBUF  (64 * SE_STRIDE)    // split E: 5120
// dynamic smem layout
#define O_WH   0
#define O_WL   (O_WH + 2 * WBUF)          // 33792
#define O_ER   (O_WL + 2 * WBUF)          // 67584
#define O_EH   (O_ER + 2 * ERBUF)         // 83968
#define O_EL   (O_EH + ESBUF)             // 89088
#define O_SV   (O_EL + ESBUF)             // 94208
#define O_SDP  (O_SV + AD * 4)            // 95232
#define O_SP   (O_SDP + AD * 4)           // 96256
#define SMEM_SC (O_SP + 4 * 64 * 4)       // 97280

__global__ __launch_bounds__(256, 2)
void k_scores_mma(const float* __restrict__ enc, const float* __restrict__ v) {
    extern __shared__ __align__(16) uint8_t smem[];
    const uint32_t sb = smem_u32(smem);

    const int tid  = threadIdx.x;
    const int w    = tid >> 5;
    const int lane = tid & 31;
    const int b    = blockIdx.y;
    const int s0   = blockIdx.x * 64;

    const int wm = (w & 1) * 32;     // warp M offset
    const int wn = (w >> 1);         // warp N quarter (64 cols at wn*64)

    float* sv  = (float*)(smem + O_SV);
    float* sdp = (float*)(smem + O_SDP);
    float* sp  = (float*)(smem + O_SP);       // [4][64]
    sv[tid]  = v[tid];
    sdp[tid] = g_dec_proj[b * AD + tid];

    const float* Eb = enc + ((size_t)b * SS + s0) * ENCD;

    // ldmatrix per-lane offsets
    const int li = lane >> 3, l7 = lane & 7;
    uint32_t aOff[2];
#pragma unroll
    for (int mt = 0; mt < 2; mt++) {
        int m = wm + mt * 16 + (li & 1) * 8 + l7;
        int k = (li >> 1) * 8;
        aOff[mt] = m * SE_STRIDE + k * 2;
    }
    uint32_t bOff[4];
#pragma unroll
    for (int p = 0; p < 4; p++) {
        int k = (li & 1) * 8 + l7;
        int n = wn * 64 + p * 16 + (li >> 1) * 8;
        bOff[p] = k * SW_STRIDE + n * 2;
    }

    float acc[2][8][4];
#pragma unroll
    for (int mt = 0; mt < 2; mt++)
#pragma unroll
        for (int j = 0; j < 8; j++)
#pragma unroll
            for (int r = 0; r < 4; r++) acc[mt][j][r] = 0.f;

    const int er = tid >> 3, ecg = (tid & 7) * 4;     // convert: row group, f32 col group

    // ---- prologue: chunk 0 ----
#pragma unroll
    for (int i = 0; i < 4; i++) {
        int idx = tid + i * 256;
        int row = idx >> 5, seg = idx & 31;
        cp16(sb + O_WH + row * SW_STRIDE + seg * 16, g_w_hi + (size_t)row * AD + seg * 8);
        cp16(sb + O_WL + row * SW_STRIDE + seg * 16, g_w_lo + (size_t)row * AD + seg * 8);
    }
#pragma unroll
    for (int i = 0; i < 2; i++) {
        int idx = tid + i * 256;
        int row = idx >> 3, seg = idx & 7;
        cp16(sb + O_ER + row * 128 + seg * 16, Eb + (size_t)row * ENCD + seg * 4);
    }
    CP_COMMIT();

#pragma unroll 1
    for (int c = 0; c < 32; c++) {
        const int buf = c & 1;
        const uint32_t uEh = sb + O_EH;
        const uint32_t uEl = sb + O_EL;
        const uint32_t uWh = sb + O_WH + buf * WBUF;
        const uint32_t uWl = sb + O_WL + buf * WBUF;

        CP_WAIT0();
        __syncthreads();          // chunk-c data visible to all; compute(c-1) fully done

        // convert raw E(c) -> split hi/lo
        {
            const uint8_t* erb = smem + O_ER + buf * ERBUF;
#pragma unroll
            for (int j = 0; j < 2; j++) {
                int r = er + j * 32;
                float4 x = *(const float4*)(erb + r * 128 + ecg * 4);
                __nv_bfloat16 h0 = __float2bfloat16_rn(x.x), h1 = __float2bfloat16_rn(x.y);
                __nv_bfloat16 h2 = __float2bfloat16_rn(x.z), h3 = __float2bfloat16_rn(x.w);
                __nv_bfloat16 l0 = __float2bfloat16_rn(x.x - __bfloat162float(h0));
                __nv_bfloat16 l1 = __float2bfloat16_rn(x.y - __bfloat162float(h1));
                __nv_bfloat16 l2 = __float2bfloat16_rn(x.z - __bfloat162float(h2));
                __nv_bfloat16 l3 = __float2bfloat16_rn(x.w - __bfloat162float(h3));
                uint32_t off = r * SE_STRIDE + ecg * 2;
                *(uint2*)(smem + O_EH + off) = make_uint2(pkbf(h0, h1), pkbf(h2, h3));
                *(uint2*)(smem + O_EL + off) = make_uint2(pkbf(l0, l1), pkbf(l2, l3));
            }
        }

        // prefetch chunk c+1 into other buffers (overlaps with compute below)
        if (c < 31) {
            const int k1 = (c + 1) * 32;
            const uint32_t ob = (c + 1) & 1;
#pragma unroll
            for (int i = 0; i < 4; i++) {
                int idx = tid + i * 256;
                int row = idx >> 5, seg = idx & 31;
                cp16(sb + O_WH + ob * WBUF + row * SW_STRIDE + seg * 16,
                     g_w_hi + (size_t)(k1 + row) * AD + seg * 8);
                cp16(sb + O_WL + ob * WBUF + row * SW_STRIDE + seg * 16,
                     g_w_lo + (size_t)(k1 + row) * AD + seg * 8);
            }
#pragma unroll
            for (int i = 0; i < 2; i++) {
                int idx = tid + i * 256;
                int row = idx >> 3, seg = idx & 7;
                cp16(sb + O_ER + ob * ERBUF + row * 128 + seg * 16,
                     Eb + (size_t)row * ENCD + k1 + seg * 4);
            }
            CP_COMMIT();
        }
        __syncthreads();          // split E ready

        // ---- compute: 2 x k16, term-major (consecutive MMAs hit distinct accs) ----
#pragma unroll
        for (int ks = 0; ks < 2; ks++) {
            const uint32_t dA = ks * 32;
            const uint32_t dB = ks * 16 * SW_STRIDE;
            uint32_t AH[2][4], AL[2][4];
#pragma unroll
            for (int mt = 0; mt < 2; mt++) {
                ldsm_x4(AH[mt], uEh + aOff[mt] + dA);
                ldsm_x4(AL[mt], uEl + aOff[mt] + dA);
            }
#pragma unroll
            for (int p = 0; p < 4; p++) {
                uint32_t BH[4], BL[4];
                ldsm_x4t(BH, uWh + bOff[p] + dB);
                ldsm_x4t(BL, uWl + bOff[p] + dB);
                // HH on all 4 accumulators, then HL, then LH
#pragma unroll
                for (int mt = 0; mt < 2; mt++)
#pragma unroll
                    for (int nt = 0; nt < 2; nt++)
                        mma16816(acc[mt][p * 2 + nt], AH[mt], BH + nt * 2);
#pragma unroll
                for (int mt = 0; mt < 2; mt++)
#pragma unroll
                    for (int nt = 0; nt < 2; nt++)
                        mma16816(acc[mt][p * 2 + nt], AH[mt], BL + nt * 2);
#pragma unroll
                for (int mt = 0; mt < 2; mt++)
#pragma unroll
                    for (int nt = 0; nt < 2; nt++)
                        mma16816(acc[mt][p * 2 + nt], AL[mt], BH + nt * 2);
            }
        }
        // no trailing sync: next iteration's post-wait sync covers WAR on split E / W buffers
    }

    __syncthreads();

    // ---- epilogue: score_m = sum_n v[n] * tanh(dp[n] + D[m][n]) ----
    const int g = lane >> 2, tig = lane & 3;
#pragma unroll
    for (int mt = 0; mt < 2; mt++) {
        float pA = 0.f, pB = 0.f;
#pragma unroll
        for (int j = 0; j < 8; j++) {
            int c0 = wn * 64 + j * 8 + tig * 2;
            float v0 = sv[c0], v1 = sv[c0 + 1];
            float d0 = sdp[c0], d1 = sdp[c0 + 1];
            pA += v0 * tanh_f(d0 + acc[mt][j][0]);
            pA += v1 * tanh_f(d1 + acc[mt][j][1]);
            pB += v0 * tanh_f(d0 + acc[mt][j][2]);
            pB += v1 * tanh_f(d1 + acc[mt][j][3]);
        }
        pA += __shfl_xor_sync(0xffffffffu, pA, 1);
        pA += __shfl_xor_sync(0xffffffffu, pA, 2);
        pB += __shfl_xor_sync(0xffffffffu, pB, 1);
        pB += __shfl_xor_sync(0xffffffffu, pB, 2);
        if (tig == 0) {
            int rA = wm + mt * 16 + g;
            sp[wn * 64 + rA]     = pA;
            sp[wn * 64 + rA + 8] = pB;
        }
    }
    __syncthreads();
    if (tid < 64) {
        float s = sp[tid] + sp[64 + tid] + sp[128 + tid] + sp[192 + tid];
        g_scores[(size_t)b * SS + s0 + tid] = s;
    }
}

// ---------------- kernel 3: mask + softmax ----------------
__global__ __launch_bounds__(256) void k_softmax(const void* __restrict__ mask,
                                                 float* __restrict__ out_w) {
    const int b = blockIdx.x;
    const int tid = threadIdx.x;
    const float* row = g_scores + (size_t)b * SS;
    const int u8 = g_mask_is_u8;
    const uint8_t* m8 = (const uint8_t*)mask;
    const int*     m32 = (const int*)mask;

    float vals[16];
    float mx = -INFINITY;
#pragma unroll
    for (int i = 0; i < 16; i++) {
        size_t idx = (size_t)b * SS + tid + i * 256;
        int msk = u8 ? (int)m8[idx] : m32[idx];
        vals[i] = msk ? NEG_INF_F : row[tid + i * 256];
        mx = fmaxf(mx, vals[i]);
    }
#pragma unroll
    for (int m = 16; m; m >>= 1)
        mx = fmaxf(mx, __shfl_xor_sync(0xffffffffu, mx, m));
    __shared__ float redm[8];
    if ((tid & 31) == 0) redm[tid >> 5] = mx;
    __syncthreads();
    mx = redm[0];
#pragma unroll
    for (int i = 1; i < 8; i++) mx = fmaxf(mx, redm[i]);

    float sum = 0.f;
#pragma unroll
    for (int i = 0; i < 16; i++) {
        vals[i] = expf(vals[i] - mx);
        sum += vals[i];
    }
#pragma unroll
    for (int m = 16; m; m >>= 1)
        sum += __shfl_xor_sync(0xffffffffu, sum, m);
    __shared__ float reds[8];
    if ((tid & 31) == 0) reds[tid >> 5] = sum;
    __syncthreads();
    sum = 0.f;
#pragma unroll
    for (int i = 0; i < 8; i++) sum += reds[i];

    float inv = 1.f / sum;
#pragma unroll
    for (int i = 0; i < 16; i++)
        out_w[(size_t)b * SS + tid + i * 256] = vals[i] * inv;
}

// ---------------- kernel 4: context partials ----------------
__global__ __launch_bounds__(256) void k_context_part(const float* __restrict__ enc,
                                                      const float* __restrict__ w) {
    const int chunk = blockIdx.x;
    const int b = blockIdx.y;
    const int tid = threadIdx.x;
    const int s0 = chunk * CTX_SROWS;

    __shared__ float ws[CTX_SROWS];
    ws[tid] = w[(size_t)b * SS + s0 + tid];
    __syncthreads();

    const float* Eb = enc + ((size_t)b * SS + s0) * ENCD;
    const int e0 = tid * 4;

    float4 acc = make_float4(0.f, 0.f, 0.f, 0.f);
#pragma unroll 4
    for (int s = 0; s < CTX_SROWS; s++) {
        float wv = ws[s];
        float4 x = *(const float4*)(Eb + (size_t)s * ENCD + e0);
        acc.x = fmaf(wv, x.x, acc.x);
        acc.y = fmaf(wv, x.y, acc.y);
        acc.z = fmaf(wv, x.z, acc.z);
        acc.w = fmaf(wv, x.w, acc.w);
    }
    *(float4*)(g_ctx_part + ((size_t)chunk * BB + b) * ENCD + e0) = acc;
}

// ---------------- kernel 5: reduce partials ----------------
__global__ void k_context_reduce(float* __restrict__ out_ctx) {
    int i = blockIdx.x * 256 + threadIdx.x;
    float acc = 0.f;
#pragma unroll
    for (int c = 0; c < CTX_CHUNKS; c++)
        acc += g_ctx_part[(size_t)c * BB * ENCD + i];
    out_ctx[i] = acc;
}

// ---------------- launch ----------------
extern "C" void kernel_launch(void* const* d_in, const int* in_sizes, int n_in,
                              void* d_out, int out_size) {
    const float* dh   = (const float*)d_in[0];
    const float* enc  = (const float*)d_in[1];
    const void*  mask = d_in[2];
    const float* Wd   = (const float*)d_in[3];
    const float* We   = (const float*)d_in[4];
    const float* v    = (const float*)d_in[5];

    float* out     = (float*)d_out;
    float* out_ctx = out;
    float* out_w   = out + BB * ENCD;

    cudaFuncSetAttribute(k_scores_mma, cudaFuncAttributeMaxDynamicSharedMemorySize, SMEM_SC);

    k_detect_mask<<<1, 1024>>>((const unsigned int*)mask);
    k_prep_w<<<ENCD, 256>>>(We);
    k_dec_proj<<<BB, 256>>>(dh, Wd);

    dim3 g2(SS / 64, BB);
    k_scores_mma<<<g2, 256, SMEM_SC>>>(enc, v);

    k_softmax<<<BB, 256>>>(mask, out_w);

    dim3 g4(CTX_CHUNKS, BB);
    k_context_part<<<g4, 256>>>(enc, out_w);
    k_context_reduce<<<(BB * ENCD) / 256, 256>>>(out_ctx);
}

// round 14
// speedup vs baseline: 1.3714x; 1.2467x over previous
#include <cuda_runtime.h>
#include <cuda_fp16.h>
#include <cstdint>
#include <math.h>

// Problem dims (fixed)
#define BB   64
#define SS   4096
#define DECD 512
#define ENCD 1024
#define AD   256
#define NEG_INF_F (-1e10f)

#define CTX_CHUNKS 16
#define CTX_SROWS  (SS / CTX_CHUNKS)   // 256

// ---------------- scratch ----------------
__device__ float g_dec_proj[BB * AD];
__device__ float g_scores[BB * SS];
__device__ __align__(16) float g_ctx_part[CTX_CHUNKS * BB * ENCD];
__device__ int   g_mask_is_u8;
// W_enc split to fp16 hi/lo, [k][n] row-major (hi+lo captures W to ~2^-24)
__device__ __align__(16) __half g_w_hi[ENCD * AD];
__device__ __align__(16) __half g_w_lo[ENCD * AD];

// ---------------- helpers ----------------
__device__ __forceinline__ uint32_t smem_u32(const void* p) {
    uint32_t a;
    asm("{ .reg .u64 t; cvta.to.shared.u64 t, %1; cvt.u32.u64 %0, t; }" : "=r"(a) : "l"(p));
    return a;
}
__device__ __forceinline__ void ldsm_x4(uint32_t* r, uint32_t addr) {
    asm volatile("ldmatrix.sync.aligned.m8n8.x4.shared.b16 {%0,%1,%2,%3}, [%4];"
        : "=r"(r[0]), "=r"(r[1]), "=r"(r[2]), "=r"(r[3]) : "r"(addr));
}
__device__ __forceinline__ void ldsm_x4t(uint32_t* r, uint32_t addr) {
    asm volatile("ldmatrix.sync.aligned.m8n8.x4.trans.shared.b16 {%0,%1,%2,%3}, [%4];"
        : "=r"(r[0]), "=r"(r[1]), "=r"(r[2]), "=r"(r[3]) : "r"(addr));
}
// fp16 inputs, fp32 accumulate
__device__ __forceinline__ void mma16816(float* d, const uint32_t* a, const uint32_t* b) {
    asm volatile("mma.sync.aligned.m16n8k16.row.col.f32.f16.f16.f32 "
        "{%0,%1,%2,%3}, {%4,%5,%6,%7}, {%8,%9}, {%0,%1,%2,%3};"
        : "+f"(d[0]), "+f"(d[1]), "+f"(d[2]), "+f"(d[3])
        : "r"(a[0]), "r"(a[1]), "r"(a[2]), "r"(a[3]), "r"(b[0]), "r"(b[1]));
}
__device__ __forceinline__ void cp16(uint32_t sdst, const void* gsrc) {
    asm volatile("cp.async.cg.shared.global [%0], [%1], 16;" :: "r"(sdst), "l"(gsrc));
}
#define CP_COMMIT() asm volatile("cp.async.commit_group;" ::: "memory")
#define CP_WAIT0()  asm volatile("cp.async.wait_group 0;" ::: "memory")

__device__ __forceinline__ uint32_t pkhf(__half a, __half b) {
    uint16_t ua = *(uint16_t*)&a, ub = *(uint16_t*)&b;
    return (uint32_t)ua | ((uint32_t)ub << 16);
}
__device__ __forceinline__ float tanh_f(float x) {
    float e = __expf(2.0f * x);
    return 1.0f - __fdividef(2.0f, e + 1.0f);
}

// ---------------- kernel 0: detect mask dtype ----------------
__global__ void k_detect_mask(const unsigned int* __restrict__ m) {
    unsigned int v = m[threadIdx.x];
    int any = __syncthreads_or(v > 1u);
    if (threadIdx.x == 0) g_mask_is_u8 = any;
}

// ---------------- kernel 0b: split W_enc into fp16 hi/lo ----------------
__global__ void k_prep_w(const float* __restrict__ We) {
    int k = blockIdx.x;
    int n = threadIdx.x;
    float x = We[(size_t)k * AD + n];
    __half h = __float2half_rn(x);
    __half l = __float2half_rn(x - __half2float(h));
    g_w_hi[(size_t)k * AD + n] = h;
    g_w_lo[(size_t)k * AD + n] = l;
}

// ---------------- kernel 1: dec_proj ----------------
__global__ void k_dec_proj(const float* __restrict__ dh, const float* __restrict__ Wd) {
    int b = blockIdx.x;
    int a = threadIdx.x;
    const float* dhb = dh + b * DECD;
    float acc = 0.f;
#pragma unroll 8
    for (int d = 0; d < DECD; d++)
        acc = fmaf(dhb[d], Wd[d * AD + a], acc);
    g_dec_proj[b * AD + a] = acc;
}

// ---------------- kernel 2: mma.sync 2-term fp16 scores GEMM (proven r9 schedule) ----------------
// CTA: 256 thr / 8 warps, tile M=64 x N=256. Warp tile 32x64, 2 CTAs/SM.
// D = E16 * (Wh + Wl): E single fp16 rounding, W split to fp16 hi/lo.
#define SE_STRIDE 80     // bytes per E row (64 data + 16 pad)
#define SW_STRIDE 528    // bytes per W row (512 data + 16 pad)
#define WBUF   (32 * SW_STRIDE)    // 16896
#define ERBUF  (64 * 128)          // raw E: 64 rows x 32 f32 = 8192
#define ESBUF  (64 * SE_STRIDE)    // fp16 E: 5120 (single buffer)
// dynamic smem layout
#define O_WH   0
#define O_WL   (O_WH + 2 * WBUF)          // 33792
#define O_ER   (O_WL + 2 * WBUF)          // 67584
#define O_ES   (O_ER + 2 * ERBUF)         // 83968
#define O_SV   (O_ES + ESBUF)             // 89088
#define O_SDP  (O_SV + AD * 4)            // 90112
#define O_SP   (O_SDP + AD * 4)           // 91136
#define SMEM_SC (O_SP + 4 * 64 * 4)       // 92160

__global__ __launch_bounds__(256, 2)
void k_scores_mma(const float* __restrict__ enc, const float* __restrict__ v) {
    extern __shared__ __align__(16) uint8_t smem[];
    const uint32_t sb = smem_u32(smem);

    const int tid  = threadIdx.x;
    const int w    = tid >> 5;
    const int lane = tid & 31;
    const int b    = blockIdx.y;
    const int s0   = blockIdx.x * 64;

    const int wm = (w & 1) * 32;     // warp M offset
    const int wn = (w >> 1);         // warp N quarter (64 cols at wn*64)

    float* sv  = (float*)(smem + O_SV);
    float* sdp = (float*)(smem + O_SDP);
    float* sp  = (float*)(smem + O_SP);       // [4][64]
    sv[tid]  = v[tid];
    sdp[tid] = g_dec_proj[b * AD + tid];

    const float* Eb = enc + ((size_t)b * SS + s0) * ENCD;

    // ldmatrix per-lane offsets
    const int li = lane >> 3, l7 = lane & 7;
    uint32_t aOff[2];
#pragma unroll
    for (int mt = 0; mt < 2; mt++) {
        int m = wm + mt * 16 + (li & 1) * 8 + l7;
        int k = (li >> 1) * 8;
        aOff[mt] = m * SE_STRIDE + k * 2;
    }
    uint32_t bOff[4];
#pragma unroll
    for (int p = 0; p < 4; p++) {
        int k = (li & 1) * 8 + l7;
        int n = wn * 64 + p * 16 + (li >> 1) * 8;
        bOff[p] = k * SW_STRIDE + n * 2;
    }

    float acc[2][8][4];
#pragma unroll
    for (int mt = 0; mt < 2; mt++)
#pragma unroll
        for (int j = 0; j < 8; j++)
#pragma unroll
            for (int r = 0; r < 4; r++) acc[mt][j][r] = 0.f;

    const int er = tid >> 3, ecg = (tid & 7) * 4;     // convert: row group, f32 col group

    // ---- prologue: chunk 0 ----
#pragma unroll
    for (int i = 0; i < 4; i++) {
        int idx = tid + i * 256;
        int row = idx >> 5, seg = idx & 31;
        cp16(sb + O_WH + row * SW_STRIDE + seg * 16, g_w_hi + (size_t)row * AD + seg * 8);
        cp16(sb + O_WL + row * SW_STRIDE + seg * 16, g_w_lo + (size_t)row * AD + seg * 8);
    }
#pragma unroll
    for (int i = 0; i < 2; i++) {
        int idx = tid + i * 256;
        int row = idx >> 3, seg = idx & 7;
        cp16(sb + O_ER + row * 128 + seg * 16, Eb + (size_t)row * ENCD + seg * 4);
    }
    CP_COMMIT();

#pragma unroll 1
    for (int c = 0; c < 32; c++) {
        const int buf = c & 1;
        const uint32_t uES = sb + O_ES;
        const uint32_t uWh = sb + O_WH + buf * WBUF;
        const uint32_t uWl = sb + O_WL + buf * WBUF;

        CP_WAIT0();
        __syncthreads();          // chunk-c data visible to all; compute(c-1) fully done

        // convert raw E(c) -> fp16 (single rounding)
        {
            const uint8_t* erb = smem + O_ER + buf * ERBUF;
#pragma unroll
            for (int j = 0; j < 2; j++) {
                int r = er + j * 32;
                float4 x = *(const float4*)(erb + r * 128 + ecg * 4);
                __half h0 = __float2half_rn(x.x), h1 = __float2half_rn(x.y);
                __half h2 = __float2half_rn(x.z), h3 = __float2half_rn(x.w);
                uint32_t off = r * SE_STRIDE + ecg * 2;
                *(uint2*)(smem + O_ES + off) = make_uint2(pkhf(h0, h1), pkhf(h2, h3));
            }
        }

        // prefetch chunk c+1 into other buffers (overlaps with compute below)
        if (c < 31) {
            const int k1 = (c + 1) * 32;
            const uint32_t ob = (c + 1) & 1;
#pragma unroll
            for (int i = 0; i < 4; i++) {
                int idx = tid + i * 256;
                int row = idx >> 5, seg = idx & 31;
                cp16(sb + O_WH + ob * WBUF + row * SW_STRIDE + seg * 16,
                     g_w_hi + (size_t)(k1 + row) * AD + seg * 8);
                cp16(sb + O_WL + ob * WBUF + row * SW_STRIDE + seg * 16,
                     g_w_lo + (size_t)(k1 + row) * AD + seg * 8);
            }
#pragma unroll
            for (int i = 0; i < 2; i++) {
                int idx = tid + i * 256;
                int row = idx >> 3, seg = idx & 7;
                cp16(sb + O_ER + ob * ERBUF + row * 128 + seg * 16,
                     Eb + (size_t)row * ENCD + k1 + seg * 4);
            }
            CP_COMMIT();
        }
        __syncthreads();          // fp16 E ready

        // ---- compute: 2 x k16, 2 terms (E.Wh + E.Wl) ----
#pragma unroll
        for (int ks = 0; ks < 2; ks++) {
            const uint32_t dA = ks * 32;
            const uint32_t dB = ks * 16 * SW_STRIDE;
            uint32_t A[2][4];
#pragma unroll
            for (int mt = 0; mt < 2; mt++)
                ldsm_x4(A[mt], uES + aOff[mt] + dA);
#pragma unroll
            for (int p = 0; p < 4; p++) {
                uint32_t BH[4], BL[4];
                ldsm_x4t(BH, uWh + bOff[p] + dB);
                ldsm_x4t(BL, uWl + bOff[p] + dB);
#pragma unroll
                for (int mt = 0; mt < 2; mt++)
#pragma unroll
                    for (int nt = 0; nt < 2; nt++)
                        mma16816(acc[mt][p * 2 + nt], A[mt], BH + nt * 2);
#pragma unroll
                for (int mt = 0; mt < 2; mt++)
#pragma unroll
                    for (int nt = 0; nt < 2; nt++)
                        mma16816(acc[mt][p * 2 + nt], A[mt], BL + nt * 2);
            }
        }
        // no trailing sync: next iteration's post-wait sync covers WAR on E/W buffers
    }

    __syncthreads();

    // ---- epilogue: score_m = sum_n v[n] * tanh(dp[n] + D[m][n]) ----
    const int g = lane >> 2, tig = lane & 3;
#pragma unroll
    for (int mt = 0; mt < 2; mt++) {
        float pA = 0.f, pB = 0.f;
#pragma unroll
        for (int j = 0; j < 8; j++) {
            int c0 = wn * 64 + j * 8 + tig * 2;
            float v0 = sv[c0], v1 = sv[c0 + 1];
            float d0 = sdp[c0], d1 = sdp[c0 + 1];
            pA += v0 * tanh_f(d0 + acc[mt][j][0]);
            pA += v1 * tanh_f(d1 + acc[mt][j][1]);
            pB += v0 * tanh_f(d0 + acc[mt][j][2]);
            pB += v1 * tanh_f(d1 + acc[mt][j][3]);
        }
        pA += __shfl_xor_sync(0xffffffffu, pA, 1);
        pA += __shfl_xor_sync(0xffffffffu, pA, 2);
        pB += __shfl_xor_sync(0xffffffffu, pB, 1);
        pB += __shfl_xor_sync(0xffffffffu, pB, 2);
        if (tig == 0) {
            int rA = wm + mt * 16 + g;
            sp[wn * 64 + rA]     = pA;
            sp[wn * 64 + rA + 8] = pB;
        }
    }
    __syncthreads();
    if (tid < 64) {
        float s = sp[tid] + sp[64 + tid] + sp[128 + tid] + sp[192 + tid];
        g_scores[(size_t)b * SS + s0 + tid] = s;
    }
}

// ---------------- kernel 3: mask + softmax ----------------
__global__ __launch_bounds__(256) void k_softmax(const void* __restrict__ mask,
                                                 float* __restrict__ out_w) {
    const int b = blockIdx.x;
    const int tid = threadIdx.x;
    const float* row = g_scores + (size_t)b * SS;
    const int u8 = g_mask_is_u8;
    const uint8_t* m8 = (const uint8_t*)mask;
    const int*     m32 = (const int*)mask;

    float vals[16];
    float mx = -INFINITY;
#pragma unroll
    for (int i = 0; i < 16; i++) {
        size_t idx = (size_t)b * SS + tid + i * 256;
        int msk = u8 ? (int)m8[idx] : m32[idx];
        vals[i] = msk ? NEG_INF_F : row[tid + i * 256];
        mx = fmaxf(mx, vals[i]);
    }
#pragma unroll
    for (int m = 16; m; m >>= 1)
        mx = fmaxf(mx, __shfl_xor_sync(0xffffffffu, mx, m));
    __shared__ float redm[8];
    if ((tid & 31) == 0) redm[tid >> 5] = mx;
    __syncthreads();
    mx = redm[0];
#pragma unroll
    for (int i = 1; i < 8; i++) mx = fmaxf(mx, redm[i]);

    float sum = 0.f;
#pragma unroll
    for (int i = 0; i < 16; i++) {
        vals[i] = expf(vals[i] - mx);
        sum += vals[i];
    }
#pragma unroll
    for (int m = 16; m; m >>= 1)
        sum += __shfl_xor_sync(0xffffffffu, sum, m);
    __shared__ float reds[8];
    if ((tid & 31) == 0) reds[tid >> 5] = sum;
    __syncthreads();
    sum = 0.f;
#pragma unroll
    for (int i = 0; i < 8; i++) sum += reds[i];

    float inv = 1.f / sum;
#pragma unroll
    for (int i = 0; i < 16; i++)
        out_w[(size_t)b * SS + tid + i * 256] = vals[i] * inv;
}

// ---------------- kernel 4: context partials ----------------
__global__ __launch_bounds__(256) void k_context_part(const float* __restrict__ enc,
                                                      const float* __restrict__ w) {
    const int chunk = blockIdx.x;
    const int b = blockIdx.y;
    const int tid = threadIdx.x;
    const int s0 = chunk * CTX_SROWS;

    __shared__ float ws[CTX_SROWS];
    ws[tid] = w[(size_t)b * SS + s0 + tid];
    __syncthreads();

    const float* Eb = enc + ((size_t)b * SS + s0) * ENCD;
    const int e0 = tid * 4;

    float4 acc = make_float4(0.f, 0.f, 0.f, 0.f);
#pragma unroll 4
    for (int s = 0; s < CTX_SROWS; s++) {
        float wv = ws[s];
        float4 x = *(const float4*)(Eb + (size_t)s * ENCD + e0);
        acc.x = fmaf(wv, x.x, acc.x);
        acc.y = fmaf(wv, x.y, acc.y);
        acc.z = fmaf(wv, x.z, acc.z);
        acc.w = fmaf(wv, x.w, acc.w);
    }
    *(float4*)(g_ctx_part + ((size_t)chunk * BB + b) * ENCD + e0) = acc;
}

// ---------------- kernel 5: reduce partials ----------------
__global__ void k_context_reduce(float* __restrict__ out_ctx) {
    int i = blockIdx.x * 256 + threadIdx.x;
    float acc = 0.f;
#pragma unroll
    for (int c = 0; c < CTX_CHUNKS; c++)
        acc += g_ctx_part[(size_t)c * BB * ENCD + i];
    out_ctx[i] = acc;
}

// ---------------- launch ----------------
extern "C" void kernel_launch(void* const* d_in, const int* in_sizes, int n_in,
                              void* d_out, int out_size) {
    const float* dh   = (const float*)d_in[0];
    const float* enc  = (const float*)d_in[1];
    const void*  mask = d_in[2];
    const float* Wd   = (const float*)d_in[3];
    const float* We   = (const float*)d_in[4];
    const float* v    = (const float*)d_in[5];

    float* out     = (float*)d_out;
    float* out_ctx = out;
    float* out_w   = out + BB * ENCD;

    cudaFuncSetAttribute(k_scores_mma, cudaFuncAttributeMaxDynamicSharedMemorySize, SMEM_SC);

    k_detect_mask<<<1, 1024>>>((const unsigned int*)mask);
    k_prep_w<<<ENCD, 256>>>(We);
    k_dec_proj<<<BB, 256>>>(dh, Wd);

    dim3 g2(SS / 64, BB);
    k_scores_mma<<<g2, 256, SMEM_SC>>>(enc, v);

    k_softmax<<<BB, 256>>>(mask, out_w);

    dim3 g4(CTX_CHUNKS, BB);
    k_context_part<<<g4, 256>>>(enc, out_w);
    k_context_reduce<<<(BB * ENCD) / 256, 256>>>(out_ctx);
}

// round 16
// speedup vs baseline: 1.8510x; 1.3497x over previous
#include <cuda_runtime.h>
#include <cuda_fp16.h>
#include <cstdint>
#include <math.h>

// Problem dims (fixed)
#define BB   64
#define SS   4096
#define DECD 512
#define ENCD 1024
#define AD   256
#define NEG_INF_F (-1e10f)

#define CTX_CHUNKS 16
#define CTX_SROWS  (SS / CTX_CHUNKS)   // 256

// ---------------- scratch ----------------
__device__ float g_dec_proj[BB * AD];
__device__ float g_scores[BB * SS];
__device__ __align__(16) float g_ctx_part[CTX_CHUNKS * BB * ENCD];
__device__ int   g_mask_is_u8;
// W_enc as fp16, [k][n] row-major
__device__ __align__(16) __half g_w16[ENCD * AD];

// ---------------- helpers ----------------
__device__ __forceinline__ uint32_t smem_u32(const void* p) {
    uint32_t a;
    asm("{ .reg .u64 t; cvta.to.shared.u64 t, %1; cvt.u32.u64 %0, t; }" : "=r"(a) : "l"(p));
    return a;
}
__device__ __forceinline__ void ldsm_x4(uint32_t* r, uint32_t addr) {
    asm volatile("ldmatrix.sync.aligned.m8n8.x4.shared.b16 {%0,%1,%2,%3}, [%4];"
        : "=r"(r[0]), "=r"(r[1]), "=r"(r[2]), "=r"(r[3]) : "r"(addr));
}
__device__ __forceinline__ void ldsm_x4t(uint32_t* r, uint32_t addr) {
    asm volatile("ldmatrix.sync.aligned.m8n8.x4.trans.shared.b16 {%0,%1,%2,%3}, [%4];"
        : "=r"(r[0]), "=r"(r[1]), "=r"(r[2]), "=r"(r[3]) : "r"(addr));
}
// fp16 inputs, fp32 accumulate
__device__ __forceinline__ void mma16816(float* d, const uint32_t* a, const uint32_t* b) {
    asm volatile("mma.sync.aligned.m16n8k16.row.col.f32.f16.f16.f32 "
        "{%0,%1,%2,%3}, {%4,%5,%6,%7}, {%8,%9}, {%0,%1,%2,%3};"
        : "+f"(d[0]), "+f"(d[1]), "+f"(d[2]), "+f"(d[3])
        : "r"(a[0]), "r"(a[1]), "r"(a[2]), "r"(a[3]), "r"(b[0]), "r"(b[1]));
}
__device__ __forceinline__ void cp16(uint32_t sdst, const void* gsrc) {
    asm volatile("cp.async.cg.shared.global [%0], [%1], 16;" :: "r"(sdst), "l"(gsrc));
}
#define CP_COMMIT() asm volatile("cp.async.commit_group;" ::: "memory")
#define CP_WAIT0()  asm volatile("cp.async.wait_group 0;" ::: "memory")

__device__ __forceinline__ uint32_t pkhf(__half a, __half b) {
    uint16_t ua = *(uint16_t*)&a, ub = *(uint16_t*)&b;
    return (uint32_t)ua | ((uint32_t)ub << 16);
}
__device__ __forceinline__ float tanh_f(float x) {
    float e = __expf(2.0f * x);
    return 1.0f - __fdividef(2.0f, e + 1.0f);
}

// ---------------- kernel 0: detect mask dtype ----------------
__global__ void k_detect_mask(const unsigned int* __restrict__ m) {
    unsigned int v = m[threadIdx.x];
    int any = __syncthreads_or(v > 1u);
    if (threadIdx.x == 0) g_mask_is_u8 = any;
}

// ---------------- kernel 0b: convert W_enc to fp16 ----------------
__global__ void k_prep_w(const float* __restrict__ We) {
    int k = blockIdx.x;
    int n = threadIdx.x;
    g_w16[(size_t)k * AD + n] = __float2half_rn(We[(size_t)k * AD + n]);
}

// ---------------- kernel 1: dec_proj ----------------
__global__ void k_dec_proj(const float* __restrict__ dh, const float* __restrict__ Wd) {
    int b = blockIdx.x;
    int a = threadIdx.x;
    const float* dhb = dh + b * DECD;
    float acc = 0.f;
#pragma unroll 8
    for (int d = 0; d < DECD; d++)
        acc = fmaf(dhb[d], Wd[d * AD + a], acc);
    g_dec_proj[b * AD + a] = acc;
}

// ---------------- kernel 2: mma.sync 1-term fp16 scores GEMM (proven r9 schedule) ----------------
// CTA: 256 thr / 8 warps, tile M=64 x N=256. Warp tile 32x64, 2 CTAs/SM.
// D = E16 * W16 (single fp16 rounding on each factor; combined rel_err ~2e-4).
#define SE_STRIDE 80     // bytes per E row (64 data + 16 pad)
#define SW_STRIDE 528    // bytes per W row (512 data + 16 pad)
#define WBUF   (32 * SW_STRIDE)    // 16896
#define ERBUF  (64 * 128)          // raw E: 64 rows x 32 f32 = 8192
#define ESBUF  (64 * SE_STRIDE)    // fp16 E: 5120 (single buffer)
// dynamic smem layout
#define O_WH   0
#define O_ER   (O_WH + 2 * WBUF)          // 33792
#define O_ES   (O_ER + 2 * ERBUF)         // 50176
#define O_SV   (O_ES + ESBUF)             // 55296
#define O_SDP  (O_SV + AD * 4)            // 56320
#define O_SP   (O_SDP + AD * 4)           // 57344
#define SMEM_SC (O_SP + 4 * 64 * 4)       // 58368

__global__ __launch_bounds__(256, 2)
void k_scores_mma(const float* __restrict__ enc, const float* __restrict__ v) {
    extern __shared__ __align__(16) uint8_t smem[];
    const uint32_t sb = smem_u32(smem);

    const int tid  = threadIdx.x;
    const int w    = tid >> 5;
    const int lane = tid & 31;
    const int b    = blockIdx.y;
    const int s0   = blockIdx.x * 64;

    const int wm = (w & 1) * 32;     // warp M offset
    const int wn = (w >> 1);         // warp N quarter (64 cols at wn*64)

    float* sv  = (float*)(smem + O_SV);
    float* sdp = (float*)(smem + O_SDP);
    float* sp  = (float*)(smem + O_SP);       // [4][64]
    sv[tid]  = v[tid];
    sdp[tid] = g_dec_proj[b * AD + tid];

    const float* Eb = enc + ((size_t)b * SS + s0) * ENCD;

    // ldmatrix per-lane offsets
    const int li = lane >> 3, l7 = lane & 7;
    uint32_t aOff[2];
#pragma unroll
    for (int mt = 0; mt < 2; mt++) {
        int m = wm + mt * 16 + (li & 1) * 8 + l7;
        int k = (li >> 1) * 8;
        aOff[mt] = m * SE_STRIDE + k * 2;
    }
    uint32_t bOff[4];
#pragma unroll
    for (int p = 0; p < 4; p++) {
        int k = (li & 1) * 8 + l7;
        int n = wn * 64 + p * 16 + (li >> 1) * 8;
        bOff[p] = k * SW_STRIDE + n * 2;
    }

    float acc[2][8][4];
#pragma unroll
    for (int mt = 0; mt < 2; mt++)
#pragma unroll
        for (int j = 0; j < 8; j++)
#pragma unroll
            for (int r = 0; r < 4; r++) acc[mt][j][r] = 0.f;

    const int er = tid >> 3, ecg = (tid & 7) * 4;     // convert: row group, f32 col group

    // ---- prologue: chunk 0 ----
#pragma unroll
    for (int i = 0; i < 4; i++) {
        int idx = tid + i * 256;
        int row = idx >> 5, seg = idx & 31;
        cp16(sb + O_WH + row * SW_STRIDE + seg * 16, g_w16 + (size_t)row * AD + seg * 8);
    }
#pragma unroll
    for (int i = 0; i < 2; i++) {
        int idx = tid + i * 256;
        int row = idx >> 3, seg = idx & 7;
        cp16(sb + O_ER + row * 128 + seg * 16, Eb + (size_t)row * ENCD + seg * 4);
    }
    CP_COMMIT();

#pragma unroll 1
    for (int c = 0; c < 32; c++) {
        const int buf = c & 1;
        const uint32_t uES = sb + O_ES;
        const uint32_t uWh = sb + O_WH + buf * WBUF;

        CP_WAIT0();
        __syncthreads();          // chunk-c data visible to all; compute(c-1) fully done

        // convert raw E(c) -> fp16 (single rounding)
        {
            const uint8_t* erb = smem + O_ER + buf * ERBUF;
#pragma unroll
            for (int j = 0; j < 2; j++) {
                int r = er + j * 32;
                float4 x = *(const float4*)(erb + r * 128 + ecg * 4);
                __half h0 = __float2half_rn(x.x), h1 = __float2half_rn(x.y);
                __half h2 = __float2half_rn(x.z), h3 = __float2half_rn(x.w);
                uint32_t off = r * SE_STRIDE + ecg * 2;
                *(uint2*)(smem + O_ES + off) = make_uint2(pkhf(h0, h1), pkhf(h2, h3));
            }
        }

        // prefetch chunk c+1 into other buffers (overlaps with compute below)
        if (c < 31) {
            const int k1 = (c + 1) * 32;
            const uint32_t ob = (c + 1) & 1;
#pragma unroll
            for (int i = 0; i < 4; i++) {
                int idx = tid + i * 256;
                int row = idx >> 5, seg = idx & 31;
                cp16(sb + O_WH + ob * WBUF + row * SW_STRIDE + seg * 16,
                     g_w16 + (size_t)(k1 + row) * AD + seg * 8);
            }
#pragma unroll
            for (int i = 0; i < 2; i++) {
                int idx = tid + i * 256;
                int row = idx >> 3, seg = idx & 7;
                cp16(sb + O_ER + ob * ERBUF + row * 128 + seg * 16,
                     Eb + (size_t)row * ENCD + k1 + seg * 4);
            }
            CP_COMMIT();
        }
        __syncthreads();          // fp16 E ready

        // ---- compute: 2 x k16, single term ----
#pragma unroll
        for (int ks = 0; ks < 2; ks++) {
            const uint32_t dA = ks * 32;
            const uint32_t dB = ks * 16 * SW_STRIDE;
            uint32_t A[2][4];
#pragma unroll
            for (int mt = 0; mt < 2; mt++)
                ldsm_x4(A[mt], uES + aOff[mt] + dA);
#pragma unroll
            for (int p = 0; p < 4; p++) {
                uint32_t BH[4];
                ldsm_x4t(BH, uWh + bOff[p] + dB);
#pragma unroll
                for (int mt = 0; mt < 2; mt++)
#pragma unroll
                    for (int nt = 0; nt < 2; nt++)
                        mma16816(acc[mt][p * 2 + nt], A[mt], BH + nt * 2);
            }
        }
        // no trailing sync: next iteration's post-wait sync covers WAR on E/W buffers
    }

    __syncthreads();

    // ---- epilogue: score_m = sum_n v[n] * tanh(dp[n] + D[m][n]) ----
    const int g = lane >> 2, tig = lane & 3;
#pragma unroll
    for (int mt = 0; mt < 2; mt++) {
        float pA = 0.f, pB = 0.f;
#pragma unroll
        for (int j = 0; j < 8; j++) {
            int c0 = wn * 64 + j * 8 + tig * 2;
            float v0 = sv[c0], v1 = sv[c0 + 1];
            float d0 = sdp[c0], d1 = sdp[c0 + 1];
            pA += v0 * tanh_f(d0 + acc[mt][j][0]);
            pA += v1 * tanh_f(d1 + acc[mt][j][1]);
            pB += v0 * tanh_f(d0 + acc[mt][j][2]);
            pB += v1 * tanh_f(d1 + acc[mt][j][3]);
        }
        pA += __shfl_xor_sync(0xffffffffu, pA, 1);
        pA += __shfl_xor_sync(0xffffffffu, pA, 2);
        pB += __shfl_xor_sync(0xffffffffu, pB, 1);
        pB += __shfl_xor_sync(0xffffffffu, pB, 2);
        if (tig == 0) {
            int rA = wm + mt * 16 + g;
            sp[wn * 64 + rA]     = pA;
            sp[wn * 64 + rA + 8] = pB;
        }
    }
    __syncthreads();
    if (tid < 64) {
        float s = sp[tid] + sp[64 + tid] + sp[128 + tid] + sp[192 + tid];
        g_scores[(size_t)b * SS + s0 + tid] = s;
    }
}

// ---------------- kernel 3: mask + softmax ----------------
__global__ __launch_bounds__(256) void k_softmax(const void* __restrict__ mask,
                                                 float* __restrict__ out_w) {
    const int b = blockIdx.x;
    const int tid = threadIdx.x;
    const float* row = g_scores + (size_t)b * SS;
    const int u8 = g_mask_is_u8;
    const uint8_t* m8 = (const uint8_t*)mask;
    const int*     m32 = (const int*)mask;

    float vals[16];
    float mx = -INFINITY;
#pragma unroll
    for (int i = 0; i < 16; i++) {
        size_t idx = (size_t)b * SS + tid + i * 256;
        int msk = u8 ? (int)m8[idx] : m32[idx];
        vals[i] = msk ? NEG_INF_F : row[tid + i * 256];
        mx = fmaxf(mx, vals[i]);
    }
#pragma unroll
    for (int m = 16; m; m >>= 1)
        mx = fmaxf(mx, __shfl_xor_sync(0xffffffffu, mx, m));
    __shared__ float redm[8];
    if ((tid & 31) == 0) redm[tid >> 5] = mx;
    __syncthreads();
    mx = redm[0];
#pragma unroll
    for (int i = 1; i < 8; i++) mx = fmaxf(mx, redm[i]);

    float sum = 0.f;
#pragma unroll
    for (int i = 0; i < 16; i++) {
        vals[i] = expf(vals[i] - mx);
        sum += vals[i];
    }
#pragma unroll
    for (int m = 16; m; m >>= 1)
        sum += __shfl_xor_sync(0xffffffffu, sum, m);
    __shared__ float reds[8];
    if ((tid & 31) == 0) reds[tid >> 5] = sum;
    __syncthreads();
    sum = 0.f;
#pragma unroll
    for (int i = 0; i < 8; i++) sum += reds[i];

    float inv = 1.f / sum;
#pragma unroll
    for (int i = 0; i < 16; i++)
        out_w[(size_t)b * SS + tid + i * 256] = vals[i] * inv;
}

// ---------------- kernel 4: context partials ----------------
__global__ __launch_bounds__(256) void k_context_part(const float* __restrict__ enc,
                                                      const float* __restrict__ w) {
    const int chunk = blockIdx.x;
    const int b = blockIdx.y;
    const int tid = threadIdx.x;
    const int s0 = chunk * CTX_SROWS;

    __shared__ float ws[CTX_SROWS];
    ws[tid] = w[(size_t)b * SS + s0 + tid];
    __syncthreads();

    const float* Eb = enc + ((size_t)b * SS + s0) * ENCD;
    const int e0 = tid * 4;

    float4 acc = make_float4(0.f, 0.f, 0.f, 0.f);
#pragma unroll 4
    for (int s = 0; s < CTX_SROWS; s++) {
        float wv = ws[s];
        float4 x = *(const float4*)(Eb + (size_t)s * ENCD + e0);
        acc.x = fmaf(wv, x.x, acc.x);
        acc.y = fmaf(wv, x.y, acc.y);
        acc.z = fmaf(wv, x.z, acc.z);
        acc.w = fmaf(wv, x.w, acc.w);
    }
    *(float4*)(g_ctx_part + ((size_t)chunk * BB + b) * ENCD + e0) = acc;
}

// ---------------- kernel 5: reduce partials ----------------
__global__ void k_context_reduce(float* __restrict__ out_ctx) {
    int i = blockIdx.x * 256 + threadIdx.x;
    float acc = 0.f;
#pragma unroll
    for (int c = 0; c < CTX_CHUNKS; c++)
        acc += g_ctx_part[(size_t)c * BB * ENCD + i];
    out_ctx[i] = acc;
}

// ---------------- launch ----------------
extern "C" void kernel_launch(void* const* d_in, const int* in_sizes, int n_in,
                              void* d_out, int out_size) {
    const float* dh   = (const float*)d_in[0];
    const float* enc  = (const float*)d_in[1];
    const void*  mask = d_in[2];
    const float* Wd   = (const float*)d_in[3];
    const float* We   = (const float*)d_in[4];
    const float* v    = (const float*)d_in[5];

    float* out     = (float*)d_out;
    float* out_ctx = out;
    float* out_w   = out + BB * ENCD;

    cudaFuncSetAttribute(k_scores_mma, cudaFuncAttributeMaxDynamicSharedMemorySize, SMEM_SC);

    k_detect_mask<<<1, 1024>>>((const unsigned int*)mask);
    k_prep_w<<<ENCD, 256>>>(We);
    k_dec_proj<<<BB, 256>>>(dh, Wd);

    dim3 g2(SS / 64, BB);
    k_scores_mma<<<g2, 256, SMEM_SC>>>(enc, v);

    k_softmax<<<BB, 256>>>(mask, out_w);

    dim3 g4(CTX_CHUNKS, BB);
    k_context_part<<<g4, 256>>>(enc, out_w);
    k_context_reduce<<<(BB * ENCD) / 256, 256>>>(out_ctx);
}

// round 17
// speedup vs baseline: 1.9103x; 1.0320x over previous
#include <cuda_runtime.h>
#include <cuda_fp16.h>
#include <cstdint>
#include <math.h>

// Problem dims (fixed)
#define BB   64
#define SS   4096
#define DECD 512
#define ENCD 1024
#define AD   256
#define NEG_INF_F (-1e10f)

#define CTX_CHUNKS 16
#define CTX_SROWS  (SS / CTX_CHUNKS)   // 256

// ---------------- scratch ----------------
__device__ float g_dec_proj[BB * AD];
__device__ float g_scores[BB * SS];
__device__ __align__(16) float g_ctx_part[CTX_CHUNKS * BB * ENCD];
__device__ int   g_mask_is_u8;
// W_enc as fp16, [k][n] row-major
__device__ __align__(16) __half g_w16[ENCD * AD];

// ---------------- helpers ----------------
__device__ __forceinline__ uint32_t smem_u32(const void* p) {
    uint32_t a;
    asm("{ .reg .u64 t; cvta.to.shared.u64 t, %1; cvt.u32.u64 %0, t; }" : "=r"(a) : "l"(p));
    return a;
}
__device__ __forceinline__ void ldsm_x4(uint32_t* r, uint32_t addr) {
    asm volatile("ldmatrix.sync.aligned.m8n8.x4.shared.b16 {%0,%1,%2,%3}, [%4];"
        : "=r"(r[0]), "=r"(r[1]), "=r"(r[2]), "=r"(r[3]) : "r"(addr));
}
__device__ __forceinline__ void ldsm_x4t(uint32_t* r, uint32_t addr) {
    asm volatile("ldmatrix.sync.aligned.m8n8.x4.trans.shared.b16 {%0,%1,%2,%3}, [%4];"
        : "=r"(r[0]), "=r"(r[1]), "=r"(r[2]), "=r"(r[3]) : "r"(addr));
}
// fp16 inputs, fp32 accumulate
__device__ __forceinline__ void mma16816(float* d, const uint32_t* a, const uint32_t* b) {
    asm volatile("mma.sync.aligned.m16n8k16.row.col.f32.f16.f16.f32 "
        "{%0,%1,%2,%3}, {%4,%5,%6,%7}, {%8,%9}, {%0,%1,%2,%3};"
        : "+f"(d[0]), "+f"(d[1]), "+f"(d[2]), "+f"(d[3])
        : "r"(a[0]), "r"(a[1]), "r"(a[2]), "r"(a[3]), "r"(b[0]), "r"(b[1]));
}
__device__ __forceinline__ void cp16(uint32_t sdst, const void* gsrc) {
    asm volatile("cp.async.cg.shared.global [%0], [%1], 16;" :: "r"(sdst), "l"(gsrc));
}
#define CP_COMMIT() asm volatile("cp.async.commit_group;" ::: "memory")
#define CP_WAIT0()  asm volatile("cp.async.wait_group 0;" ::: "memory")

__device__ __forceinline__ uint32_t pkhf(__half a, __half b) {
    uint16_t ua = *(uint16_t*)&a, ub = *(uint16_t*)&b;
    return (uint32_t)ua | ((uint32_t)ub << 16);
}
__device__ __forceinline__ float tanh_f(float x) {
    float e = __expf(2.0f * x);
    return 1.0f - __fdividef(2.0f, e + 1.0f);
}

// ---------------- kernel 0: detect mask dtype ----------------
__global__ void k_detect_mask(const unsigned int* __restrict__ m) {
    unsigned int v = m[threadIdx.x];
    int any = __syncthreads_or(v > 1u);
    if (threadIdx.x == 0) g_mask_is_u8 = any;
}

// ---------------- kernel 0b: convert W_enc to fp16 ----------------
__global__ void k_prep_w(const float* __restrict__ We) {
    int k = blockIdx.x;
    int n = threadIdx.x;
    g_w16[(size_t)k * AD + n] = __float2half_rn(We[(size_t)k * AD + n]);
}

// ---------------- kernel 1: dec_proj ----------------
__global__ void k_dec_proj(const float* __restrict__ dh, const float* __restrict__ Wd) {
    int b = blockIdx.x;
    int a = threadIdx.x;
    const float* dhb = dh + b * DECD;
    float acc = 0.f;
#pragma unroll 8
    for (int d = 0; d < DECD; d++)
        acc = fmaf(dhb[d], Wd[d * AD + a], acc);
    g_dec_proj[b * AD + a] = acc;
}

// ---------------- kernel 2: mma.sync 1-term fp16 scores GEMM, KC=64 chunks ----------------
// CTA: 256 thr / 8 warps, tile M=64 x N=256. Warp tile 32x64, 2 CTAs/SM.
// D = E16 * W16. 16 K-chunks of 64 (half the barriers of KC=32).
#define KC 64
#define NCH (ENCD / KC)            // 16
#define SE_STRIDE 144    // bytes per E row (128 data + 16 pad)
#define SW_STRIDE 528    // bytes per W row (512 data + 16 pad)
#define WBUF   (KC * SW_STRIDE)    // 33792
#define ERBUF  (64 * KC * 4)       // raw E: 64 rows x 64 f32 = 16384
#define ESBUF  (64 * SE_STRIDE)    // fp16 E: 9216 (single buffer)
// dynamic smem layout
#define O_WH   0
#define O_ER   (O_WH + 2 * WBUF)          // 67584
#define O_ES   (O_ER + 2 * ERBUF)         // 100352
#define O_SV   (O_ES + ESBUF)             // 109568
#define O_SDP  (O_SV + AD * 4)            // 110592
#define O_SP   (O_SDP + AD * 4)           // 111616
#define SMEM_SC (O_SP + 4 * 64 * 4)       // 112640

__global__ __launch_bounds__(256, 2)
void k_scores_mma(const float* __restrict__ enc, const float* __restrict__ v) {
    extern __shared__ __align__(16) uint8_t smem[];
    const uint32_t sb = smem_u32(smem);

    const int tid  = threadIdx.x;
    const int w    = tid >> 5;
    const int lane = tid & 31;
    const int b    = blockIdx.y;
    const int s0   = blockIdx.x * 64;

    const int wm = (w & 1) * 32;     // warp M offset
    const int wn = (w >> 1);         // warp N quarter (64 cols at wn*64)

    float* sv  = (float*)(smem + O_SV);
    float* sdp = (float*)(smem + O_SDP);
    float* sp  = (float*)(smem + O_SP);       // [4][64]
    sv[tid]  = v[tid];
    sdp[tid] = g_dec_proj[b * AD + tid];

    const float* Eb = enc + ((size_t)b * SS + s0) * ENCD;

    // ldmatrix per-lane offsets
    const int li = lane >> 3, l7 = lane & 7;
    uint32_t aOff[2];
#pragma unroll
    for (int mt = 0; mt < 2; mt++) {
        int m = wm + mt * 16 + (li & 1) * 8 + l7;
        int k = (li >> 1) * 8;
        aOff[mt] = m * SE_STRIDE + k * 2;
    }
    uint32_t bOff[4];
#pragma unroll
    for (int p = 0; p < 4; p++) {
        int k = (li & 1) * 8 + l7;
        int n = wn * 64 + p * 16 + (li >> 1) * 8;
        bOff[p] = k * SW_STRIDE + n * 2;
    }

    float acc[2][8][4];
#pragma unroll
    for (int mt = 0; mt < 2; mt++)
#pragma unroll
        for (int j = 0; j < 8; j++)
#pragma unroll
            for (int r = 0; r < 4; r++) acc[mt][j][r] = 0.f;

    // convert mapping: row r = tid>>2 (0..63), col base (tid&3)*16 (f32 cols)
    const int cr = tid >> 2, cb = (tid & 3) * 16;

    // ---- prologue: chunk 0 ----
#pragma unroll
    for (int i = 0; i < 8; i++) {
        int idx = tid + i * 256;
        int row = idx >> 5, seg = idx & 31;
        cp16(sb + O_WH + row * SW_STRIDE + seg * 16, g_w16 + (size_t)row * AD + seg * 8);
    }
#pragma unroll
    for (int i = 0; i < 4; i++) {
        int idx = tid + i * 256;
        int row = idx >> 4, seg = idx & 15;
        cp16(sb + O_ER + row * (KC * 4) + seg * 16, Eb + (size_t)row * ENCD + seg * 4);
    }
    CP_COMMIT();

#pragma unroll 1
    for (int c = 0; c < NCH; c++) {
        const int buf = c & 1;
        const uint32_t uES = sb + O_ES;
        const uint32_t uWh = sb + O_WH + buf * WBUF;

        CP_WAIT0();
        __syncthreads();          // chunk-c data visible to all; compute(c-1) fully done

        // convert raw E(c) -> fp16 (single rounding); 16 f32 per thread
        {
            const uint8_t* erb = smem + O_ER + buf * ERBUF;
#pragma unroll
            for (int j = 0; j < 4; j++) {
                float4 x = *(const float4*)(erb + cr * (KC * 4) + (cb + j * 4) * 4);
                __half h0 = __float2half_rn(x.x), h1 = __float2half_rn(x.y);
                __half h2 = __float2half_rn(x.z), h3 = __float2half_rn(x.w);
                uint32_t off = cr * SE_STRIDE + (cb + j * 4) * 2;
                *(uint2*)(smem + O_ES + off) = make_uint2(pkhf(h0, h1), pkhf(h2, h3));
            }
        }

        // prefetch chunk c+1 into other buffers (overlaps with compute below)
        if (c < NCH - 1) {
            const int k1 = (c + 1) * KC;
            const uint32_t ob = (c + 1) & 1;
#pragma unroll
            for (int i = 0; i < 8; i++) {
                int idx = tid + i * 256;
                int row = idx >> 5, seg = idx & 31;
                cp16(sb + O_WH + ob * WBUF + row * SW_STRIDE + seg * 16,
                     g_w16 + (size_t)(k1 + row) * AD + seg * 8);
            }
#pragma unroll
            for (int i = 0; i < 4; i++) {
                int idx = tid + i * 256;
                int row = idx >> 4, seg = idx & 15;
                cp16(sb + O_ER + ob * ERBUF + row * (KC * 4) + seg * 16,
                     Eb + (size_t)row * ENCD + k1 + seg * 4);
            }
            CP_COMMIT();
        }
        __syncthreads();          // fp16 E ready

        // ---- compute: 4 x k16, single term ----
#pragma unroll
        for (int ks = 0; ks < 4; ks++) {
            const uint32_t dA = ks * 32;                 // 16 fp16 = 32B
            const uint32_t dB = ks * 16 * SW_STRIDE;
            uint32_t A[2][4];
#pragma unroll
            for (int mt = 0; mt < 2; mt++)
                ldsm_x4(A[mt], uES + aOff[mt] + dA);
#pragma unroll
            for (int p = 0; p < 4; p++) {
                uint32_t BH[4];
                ldsm_x4t(BH, uWh + bOff[p] + dB);
#pragma unroll
                for (int mt = 0; mt < 2; mt++)
#pragma unroll
                    for (int nt = 0; nt < 2; nt++)
                        mma16816(acc[mt][p * 2 + nt], A[mt], BH + nt * 2);
            }
        }
        // no trailing sync: next iteration's post-wait sync covers WAR on E/W buffers
    }

    __syncthreads();

    // ---- epilogue: score_m = sum_n v[n] * tanh(dp[n] + D[m][n]) ----
    const int g = lane >> 2, tig = lane & 3;
#pragma unroll
    for (int mt = 0; mt < 2; mt++) {
        float pA = 0.f, pB = 0.f;
#pragma unroll
        for (int j = 0; j < 8; j++) {
            int c0 = wn * 64 + j * 8 + tig * 2;
            float v0 = sv[c0], v1 = sv[c0 + 1];
            float d0 = sdp[c0], d1 = sdp[c0 + 1];
            pA += v0 * tanh_f(d0 + acc[mt][j][0]);
            pA += v1 * tanh_f(d1 + acc[mt][j][1]);
            pB += v0 * tanh_f(d0 + acc[mt][j][2]);
            pB += v1 * tanh_f(d1 + acc[mt][j][3]);
        }
        pA += __shfl_xor_sync(0xffffffffu, pA, 1);
        pA += __shfl_xor_sync(0xffffffffu, pA, 2);
        pB += __shfl_xor_sync(0xffffffffu, pB, 1);
        pB += __shfl_xor_sync(0xffffffffu, pB, 2);
        if (tig == 0) {
            int rA = wm + mt * 16 + g;
            sp[wn * 64 + rA]     = pA;
            sp[wn * 64 + rA + 8] = pB;
        }
    }
    __syncthreads();
    if (tid < 64) {
        float s = sp[tid] + sp[64 + tid] + sp[128 + tid] + sp[192 + tid];
        g_scores[(size_t)b * SS + s0 + tid] = s;
    }
}

// ---------------- kernel 3: mask + softmax ----------------
__global__ __launch_bounds__(256) void k_softmax(const void* __restrict__ mask,
                                                 float* __restrict__ out_w) {
    const int b = blockIdx.x;
    const int tid = threadIdx.x;
    const float* row = g_scores + (size_t)b * SS;
    const int u8 = g_mask_is_u8;
    const uint8_t* m8 = (const uint8_t*)mask;
    const int*     m32 = (const int*)mask;

    float vals[16];
    float mx = -INFINITY;
#pragma unroll
    for (int i = 0; i < 16; i++) {
        size_t idx = (size_t)b * SS + tid + i * 256;
        int msk = u8 ? (int)m8[idx] : m32[idx];
        vals[i] = msk ? NEG_INF_F : row[tid + i * 256];
        mx = fmaxf(mx, vals[i]);
    }
#pragma unroll
    for (int m = 16; m; m >>= 1)
        mx = fmaxf(mx, __shfl_xor_sync(0xffffffffu, mx, m));
    __shared__ float redm[8];
    if ((tid & 31) == 0) redm[tid >> 5] = mx;
    __syncthreads();
    mx = redm[0];
#pragma unroll
    for (int i = 1; i < 8; i++) mx = fmaxf(mx, redm[i]);

    float sum = 0.f;
#pragma unroll
    for (int i = 0; i < 16; i++) {
        vals[i] = expf(vals[i] - mx);
        sum += vals[i];
    }
#pragma unroll
    for (int m = 16; m; m >>= 1)
        sum += __shfl_xor_sync(0xffffffffu, sum, m);
    __shared__ float reds[8];
    if ((tid & 31) == 0) reds[tid >> 5] = sum;
    __syncthreads();
    sum = 0.f;
#pragma unroll
    for (int i = 0; i < 8; i++) sum += reds[i];

    float inv = 1.f / sum;
#pragma unroll
    for (int i = 0; i < 16; i++)
        out_w[(size_t)b * SS + tid + i * 256] = vals[i] * inv;
}

// ---------------- kernel 4: context partials ----------------
__global__ __launch_bounds__(256) void k_context_part(const float* __restrict__ enc,
                                                      const float* __restrict__ w) {
    const int chunk = blockIdx.x;
    const int b = blockIdx.y;
    const int tid = threadIdx.x;
    const int s0 = chunk * CTX_SROWS;

    __shared__ float ws[CTX_SROWS];
    ws[tid] = w[(size_t)b * SS + s0 + tid];
    __syncthreads();

    const float* Eb = enc + ((size_t)b * SS + s0) * ENCD;
    const int e0 = tid * 4;

    float4 acc = make_float4(0.f, 0.f, 0.f, 0.f);
#pragma unroll 4
    for (int s = 0; s < CTX_SROWS; s++) {
        float wv = ws[s];
        float4 x = *(const float4*)(Eb + (size_t)s * ENCD + e0);
        acc.x = fmaf(wv, x.x, acc.x);
        acc.y = fmaf(wv, x.y, acc.y);
        acc.z = fmaf(wv, x.z, acc.z);
        acc.w = fmaf(wv, x.w, acc.w);
    }
    *(float4*)(g_ctx_part + ((size_t)chunk * BB + b) * ENCD + e0) = acc;
}

// ---------------- kernel 5: reduce partials ----------------
__global__ void k_context_reduce(float* __restrict__ out_ctx) {
    int i = blockIdx.x * 256 + threadIdx.x;
    float acc = 0.f;
#pragma unroll
    for (int c = 0; c < CTX_CHUNKS; c++)
        acc += g_ctx_part[(size_t)c * BB * ENCD + i];
    out_ctx[i] = acc;
}

// ---------------- launch ----------------
extern "C" void kernel_launch(void* const* d_in, const int* in_sizes, int n_in,
                              void* d_out, int out_size) {
    const float* dh   = (const float*)d_in[0];
    const float* enc  = (const float*)d_in[1];
    const void*  mask = d_in[2];
    const float* Wd   = (const float*)d_in[3];
    const float* We   = (const float*)d_in[4];
    const float* v    = (const float*)d_in[5];

    float* out     = (float*)d_out;
    float* out_ctx = out;
    float* out_w   = out + BB * ENCD;

    cudaFuncSetAttribute(k_scores_mma, cudaFuncAttributeMaxDynamicSharedMemorySize, SMEM_SC);

    k_detect_mask<<<1, 1024>>>((const unsigned int*)mask);
    k_prep_w<<<ENCD, 256>>>(We);
    k_dec_proj<<<BB, 256>>>(dh, Wd);

    dim3 g2(SS / 64, BB);
    k_scores_mma<<<g2, 256, SMEM_SC>>>(enc, v);

    k_softmax<<<BB, 256>>>(mask, out_w);

    dim3 g4(CTX_CHUNKS, BB);
    k_context_part<<<g4, 256>>>(enc, out_w);
    k_context_reduce<<<(BB * ENCD) / 256, 256>>>(out_ctx);
}